// round 2
// baseline (speedup 1.0000x reference)
#include <cuda_runtime.h>
#include <cuda_bf16.h>
#include <math.h>

// ---------------------------------------------------------------------------
// FPGNN forward, fp32 SIMT.
// Shapes: B=512, N=128, F_IN=133, NHEADS=8, NHID=64, HID=512, FP_DIM=1489,
//         FP2=512, TASKS=12.
// Pipeline:
//   1. Wcat transpose  (W_heads [8,133,64] -> [133,512])
//   2. Wh = h2d @ Wcat                     [65536,512]
//   3. s1/s2 head scores (warp dot-64)
//   4. attn1: per-(b,h) block: masked-leaky softmax in SMEM + att@Wh + ELU
//      -> x [B,N,512] (already in concat layout)
//   5. Wx = x @ W_out                      [65536,512]
//   6. t1/t2 scores (warp dot-512)
//   7. attn2: per-b block: softmax + att2@Wx + ELU + node-mean -> gat [512,512]
//   8. FPN: relu(fp@fc1+b) @ fc2 + b
//   9. fused = q + v  (softmax over size-1 axis == 1; k-path is dead code)
//      -> relu(fused@o_w+o_b) -> relu(@ffn1+b) -> @ffn2+b -> out [512,12]
// ---------------------------------------------------------------------------

#define Bq 512
#define Nn 128
#define F_IN 133
#define NHEADS 8
#define NHID 64
#define HID 512
#define FP_DIM 1489
#define TASKS 12

// ---- scratch (device globals; no allocation allowed) ----
__device__ float g_Wcat[F_IN * HID];                    // 133x512
__device__ float g_Wh[(size_t)Bq * Nn * HID];           // 134 MB  (col = h*64+d)
__device__ float g_s1[Bq * NHEADS * Nn];
__device__ float g_s2[Bq * NHEADS * Nn];
__device__ float g_x[(size_t)Bq * Nn * HID];            // 134 MB
__device__ float g_Wx[(size_t)Bq * Nn * HID];           // 134 MB
__device__ float g_t1[Bq * Nn];
__device__ float g_t2[Bq * Nn];
__device__ float g_gat[Bq * HID];
__device__ float g_fpnh[Bq * HID];
__device__ float g_fpn[Bq * HID];
__device__ float g_buf1[Bq * HID];
__device__ float g_buf2[Bq * HID];

// ---------------------------------------------------------------------------
// Generic tiled SGEMM: C[M,N] = A[M,K] @ B[K,N] (+bias)(+relu)(+accumulate C)
// flags: 1 = add bias, 2 = relu, 4 = accumulate into existing C
// BM=BN=128, BK=8, 256 threads, 8x8 per-thread tile.
// Requires: M % 128 == 0, N % 128 == 0 (true for every call site here).
// ---------------------------------------------------------------------------
__global__ __launch_bounds__(256) void sgemm_kernel(
    const float* __restrict__ A, const float* __restrict__ B,
    const float* __restrict__ bias, float* __restrict__ C,
    int M, int N, int K, int flags)
{
    __shared__ float As[8][128];
    __shared__ float Bs[8][128];

    int tid = threadIdx.x;
    int bm = blockIdx.y * 128;
    int bn = blockIdx.x * 128;
    int tx = tid & 15;          // 0..15 -> cols tx*8..+7
    int ty = tid >> 4;          // 0..15 -> rows ty*8..+7

    int aRow = tid >> 1;        // 0..127
    int aCol = (tid & 1) * 4;   // 0 or 4
    int bRow = tid >> 5;        // 0..7
    int bCol = (tid & 31) * 4;  // 0..124

    float acc[8][8];
#pragma unroll
    for (int i = 0; i < 8; i++)
#pragma unroll
        for (int j = 0; j < 8; j++) acc[i][j] = 0.f;

    for (int k0 = 0; k0 < K; k0 += 8) {
        // load A tile (transposed into As[k][m]); K may not divide 8 -> guard k
        int row = bm + aRow;
#pragma unroll
        for (int i = 0; i < 4; i++) {
            int kk = k0 + aCol + i;
            float v = 0.f;
            if (kk < K) v = A[(size_t)row * K + kk];
            As[aCol + i][aRow] = v;
        }
        // load B tile (vectorized; N % 128 == 0 so column range always valid)
        {
            int kk = k0 + bRow;
            float4 v = make_float4(0.f, 0.f, 0.f, 0.f);
            if (kk < K) v = *(const float4*)(B + (size_t)kk * N + bn + bCol);
            *(float4*)&Bs[bRow][bCol] = v;
        }
        __syncthreads();
#pragma unroll
        for (int kk = 0; kk < 8; kk++) {
            float a[8], b[8];
#pragma unroll
            for (int i = 0; i < 8; i++) a[i] = As[kk][ty * 8 + i];
#pragma unroll
            for (int j = 0; j < 8; j++) b[j] = Bs[kk][tx * 8 + j];
#pragma unroll
            for (int i = 0; i < 8; i++)
#pragma unroll
                for (int j = 0; j < 8; j++) acc[i][j] += a[i] * b[j];
        }
        __syncthreads();
    }

#pragma unroll
    for (int i = 0; i < 8; i++) {
        int row = bm + ty * 8 + i;
#pragma unroll
        for (int j = 0; j < 8; j++) {
            int col = bn + tx * 8 + j;
            float v = acc[i][j];
            if (flags & 4) v += C[(size_t)row * N + col];
            if (flags & 1) v += bias[col];
            if (flags & 2) v = fmaxf(v, 0.f);
            C[(size_t)row * N + col] = v;
        }
    }
}

// ---------------------------------------------------------------------------
// W_heads [8,133,64] -> Wcat [133, 512]   (Wcat[f, h*64+d])
// ---------------------------------------------------------------------------
__global__ void wcat_kernel(const float* __restrict__ W_heads)
{
    int idx = blockIdx.x * blockDim.x + threadIdx.x;
    if (idx >= NHEADS * F_IN * NHID) return;
    int h = idx / (F_IN * NHID);
    int rem = idx - h * (F_IN * NHID);
    int f = rem / NHID;
    int d = rem - f * NHID;
    g_Wcat[f * HID + h * NHID + d] = W_heads[idx];
}

// ---------------------------------------------------------------------------
// s1[b,h,n] = Wh[b,h,n,:] . a1[h,:]   (warp per row, 64-length dot)
// ---------------------------------------------------------------------------
__global__ __launch_bounds__(256) void s12_kernel(
    const float* __restrict__ a1, const float* __restrict__ a2)
{
    int gw = (blockIdx.x * blockDim.x + threadIdx.x) >> 5;
    int lane = threadIdx.x & 31;
    if (gw >= Bq * NHEADS * Nn) return;
    int n  = gw & 127;
    int hh = (gw >> 7) & 7;
    int b  = gw >> 10;
    const float* row = g_Wh + ((size_t)b * Nn + n) * HID + hh * NHID;
    const float* av1 = a1 + hh * NHID;
    const float* av2 = a2 + hh * NHID;
    float x0 = row[lane], x1 = row[lane + 32];
    float r1 = x0 * av1[lane] + x1 * av1[lane + 32];
    float r2 = x0 * av2[lane] + x1 * av2[lane + 32];
#pragma unroll
    for (int o = 16; o; o >>= 1) {
        r1 += __shfl_xor_sync(0xffffffffu, r1, o);
        r2 += __shfl_xor_sync(0xffffffffu, r2, o);
    }
    if (lane == 0) {
        int o = (b * NHEADS + hh) * Nn + n;
        g_s1[o] = r1;
        g_s2[o] = r2;
    }
}

// ---------------------------------------------------------------------------
// t1[b,n] = Wx[b,n,:] . a1_out  (warp per row, 512-length dot)
// ---------------------------------------------------------------------------
__global__ __launch_bounds__(256) void t12_kernel(
    const float* __restrict__ a1, const float* __restrict__ a2)
{
    int gw = (blockIdx.x * blockDim.x + threadIdx.x) >> 5;
    int lane = threadIdx.x & 31;
    if (gw >= Bq * Nn) return;
    const float* row = g_Wx + (size_t)gw * HID;
    float r1 = 0.f, r2 = 0.f;
    for (int c = lane; c < HID; c += 32) {
        float v = row[c];
        r1 += v * a1[c];
        r2 += v * a2[c];
    }
#pragma unroll
    for (int o = 16; o; o >>= 1) {
        r1 += __shfl_xor_sync(0xffffffffu, r1, o);
        r2 += __shfl_xor_sync(0xffffffffu, r2, o);
    }
    if (lane == 0) { g_t1[gw] = r1; g_t2[gw] = r2; }
}

// ---------------------------------------------------------------------------
// attn1: per-(b,h) block. SMEM: Wh tile[128,64], att[128,128], s1/s2[128].
// Computes masked-leaky softmax, then att @ Wh, ELU, writes x[b,n,h*64+d].
// ---------------------------------------------------------------------------
__global__ __launch_bounds__(256) void attn1_kernel(
    const float* __restrict__ ae_heads, const int* __restrict__ adj,
    const float* __restrict__ edge)
{
    extern __shared__ float sm[];
    float* sWh  = sm;            // 8192 floats
    float* sAtt = sm + 8192;     // 16384 floats
    float* ss1  = sm + 24576;    // 128
    float* ss2  = sm + 24704;    // 128

    int tid = threadIdx.x;
    int bh = blockIdx.x;
    int hh = bh & 7, b = bh >> 3;
    float ae = ae_heads[hh];

    const float* whp = g_Wh + (size_t)b * Nn * HID + hh * NHID;
    for (int i = tid; i < 128 * 16; i += 256) {
        int r = i >> 4, c = i & 15;
        ((float4*)sWh)[r * 16 + c] = *((const float4*)(whp + (size_t)r * HID) + c);
    }
    if (tid < 128) {
        ss1[tid] = g_s1[bh * Nn + tid];
        ss2[tid] = g_s2[bh * Nn + tid];
    }
    __syncthreads();

    int warp = tid >> 5, lane = tid & 31;
    for (int i = warp; i < 128; i += 8) {
        float4 ef = ((const float4*)(edge + ((size_t)b * Nn + i) * Nn))[lane];
        int4  av  = ((const int4*)(adj  + ((size_t)b * Nn + i) * Nn))[lane];
        float si = ss1[i];
        int j0 = lane * 4;
        float v0 = si + ss2[j0 + 0] + ef.x * ae; v0 = v0 >= 0.f ? v0 : 0.2f * v0; v0 = av.x > 0 ? v0 : -9e15f;
        float v1 = si + ss2[j0 + 1] + ef.y * ae; v1 = v1 >= 0.f ? v1 : 0.2f * v1; v1 = av.y > 0 ? v1 : -9e15f;
        float v2 = si + ss2[j0 + 2] + ef.z * ae; v2 = v2 >= 0.f ? v2 : 0.2f * v2; v2 = av.z > 0 ? v2 : -9e15f;
        float v3 = si + ss2[j0 + 3] + ef.w * ae; v3 = v3 >= 0.f ? v3 : 0.2f * v3; v3 = av.w > 0 ? v3 : -9e15f;
        float m = fmaxf(fmaxf(v0, v1), fmaxf(v2, v3));
#pragma unroll
        for (int o = 16; o; o >>= 1) m = fmaxf(m, __shfl_xor_sync(0xffffffffu, m, o));
        float e0 = __expf(v0 - m), e1 = __expf(v1 - m), e2 = __expf(v2 - m), e3 = __expf(v3 - m);
        float s = e0 + e1 + e2 + e3;
#pragma unroll
        for (int o = 16; o; o >>= 1) s += __shfl_xor_sync(0xffffffffu, s, o);
        float inv = 1.f / s;
        float4 out; out.x = e0 * inv; out.y = e1 * inv; out.z = e2 * inv; out.w = e3 * inv;
        ((float4*)(sAtt + i * 128))[lane] = out;
    }
    __syncthreads();

    // hp = att @ Wh : thread (tx,ty) -> rows ty*8..+7, cols tx*4..+3
    int tx = tid & 15, ty = tid >> 4;
    float acc[8][4];
#pragma unroll
    for (int r = 0; r < 8; r++)
#pragma unroll
        for (int c = 0; c < 4; c++) acc[r][c] = 0.f;

    for (int j = 0; j < 128; j += 4) {
        float4 w0 = ((const float4*)(sWh + (j + 0) * 64))[tx];
        float4 w1 = ((const float4*)(sWh + (j + 1) * 64))[tx];
        float4 w2 = ((const float4*)(sWh + (j + 2) * 64))[tx];
        float4 w3 = ((const float4*)(sWh + (j + 3) * 64))[tx];
#pragma unroll
        for (int r = 0; r < 8; r++) {
            float4 a = *(const float4*)(sAtt + (ty * 8 + r) * 128 + j);
            acc[r][0] += a.x * w0.x; acc[r][1] += a.x * w0.y; acc[r][2] += a.x * w0.z; acc[r][3] += a.x * w0.w;
            acc[r][0] += a.y * w1.x; acc[r][1] += a.y * w1.y; acc[r][2] += a.y * w1.z; acc[r][3] += a.y * w1.w;
            acc[r][0] += a.z * w2.x; acc[r][1] += a.z * w2.y; acc[r][2] += a.z * w2.z; acc[r][3] += a.z * w2.w;
            acc[r][0] += a.w * w3.x; acc[r][1] += a.w * w3.y; acc[r][2] += a.w * w3.z; acc[r][3] += a.w * w3.w;
        }
    }

#pragma unroll
    for (int r = 0; r < 8; r++) {
        int i = ty * 8 + r;
        float4 o;
        float v;
        v = acc[r][0]; o.x = v > 0.f ? v : (__expf(v) - 1.f);
        v = acc[r][1]; o.y = v > 0.f ? v : (__expf(v) - 1.f);
        v = acc[r][2]; o.z = v > 0.f ? v : (__expf(v) - 1.f);
        v = acc[r][3]; o.w = v > 0.f ? v : (__expf(v) - 1.f);
        *(float4*)(g_x + ((size_t)b * Nn + i) * HID + hh * NHID + tx * 4) = o;
    }
}

// ---------------------------------------------------------------------------
// attn2: per-b block. Softmax [128,128] in SMEM, then att2 @ Wx in 8 chunks
// of 64 cols, ELU, node-mean -> g_gat[b, :512].
// ---------------------------------------------------------------------------
__global__ __launch_bounds__(256) void attn2_kernel(
    const float* __restrict__ ae_out, const int* __restrict__ adj,
    const float* __restrict__ edge)
{
    extern __shared__ float sm[];
    float* sAtt    = sm;           // 16384 floats
    float* sWx     = sm + 16384;   // 8192
    float* st1     = sm + 24576;   // 128
    float* st2     = sm + 24704;   // 128
    float* scratch = sm + 24832;   // 1024 (16 x 64)

    int tid = threadIdx.x;
    int b = blockIdx.x;
    float ae = ae_out[0];

    if (tid < 128) {
        st1[tid] = g_t1[b * Nn + tid];
        st2[tid] = g_t2[b * Nn + tid];
    }
    __syncthreads();

    int warp = tid >> 5, lane = tid & 31;
    for (int i = warp; i < 128; i += 8) {
        float4 ef = ((const float4*)(edge + ((size_t)b * Nn + i) * Nn))[lane];
        int4  av  = ((const int4*)(adj  + ((size_t)b * Nn + i) * Nn))[lane];
        float si = st1[i];
        int j0 = lane * 4;
        float v0 = si + st2[j0 + 0] + ef.x * ae; v0 = v0 >= 0.f ? v0 : 0.2f * v0; v0 = av.x > 0 ? v0 : -9e15f;
        float v1 = si + st2[j0 + 1] + ef.y * ae; v1 = v1 >= 0.f ? v1 : 0.2f * v1; v1 = av.y > 0 ? v1 : -9e15f;
        float v2 = si + st2[j0 + 2] + ef.z * ae; v2 = v2 >= 0.f ? v2 : 0.2f * v2; v2 = av.z > 0 ? v2 : -9e15f;
        float v3 = si + st2[j0 + 3] + ef.w * ae; v3 = v3 >= 0.f ? v3 : 0.2f * v3; v3 = av.w > 0 ? v3 : -9e15f;
        float m = fmaxf(fmaxf(v0, v1), fmaxf(v2, v3));
#pragma unroll
        for (int o = 16; o; o >>= 1) m = fmaxf(m, __shfl_xor_sync(0xffffffffu, m, o));
        float e0 = __expf(v0 - m), e1 = __expf(v1 - m), e2 = __expf(v2 - m), e3 = __expf(v3 - m);
        float s = e0 + e1 + e2 + e3;
#pragma unroll
        for (int o = 16; o; o >>= 1) s += __shfl_xor_sync(0xffffffffu, s, o);
        float inv = 1.f / s;
        float4 out; out.x = e0 * inv; out.y = e1 * inv; out.z = e2 * inv; out.w = e3 * inv;
        ((float4*)(sAtt + i * 128))[lane] = out;
    }
    __syncthreads();

    int tx = tid & 15, ty = tid >> 4;

    for (int ch = 0; ch < 8; ch++) {
        // load Wx[b, :, ch*64 .. ch*64+63]
        const float* wp = g_Wx + (size_t)b * Nn * HID + ch * 64;
        for (int i = tid; i < 128 * 16; i += 256) {
            int r = i >> 4, c = i & 15;
            ((float4*)sWx)[r * 16 + c] = *((const float4*)(wp + (size_t)r * HID) + c);
        }
        __syncthreads();

        float acc[8][4];
#pragma unroll
        for (int r = 0; r < 8; r++)
#pragma unroll
            for (int c = 0; c < 4; c++) acc[r][c] = 0.f;

        for (int j = 0; j < 128; j += 4) {
            float4 w0 = ((const float4*)(sWx + (j + 0) * 64))[tx];
            float4 w1 = ((const float4*)(sWx + (j + 1) * 64))[tx];
            float4 w2 = ((const float4*)(sWx + (j + 2) * 64))[tx];
            float4 w3 = ((const float4*)(sWx + (j + 3) * 64))[tx];
#pragma unroll
            for (int r = 0; r < 8; r++) {
                float4 a = *(const float4*)(sAtt + (ty * 8 + r) * 128 + j);
                acc[r][0] += a.x * w0.x; acc[r][1] += a.x * w0.y; acc[r][2] += a.x * w0.z; acc[r][3] += a.x * w0.w;
                acc[r][0] += a.y * w1.x; acc[r][1] += a.y * w1.y; acc[r][2] += a.y * w1.z; acc[r][3] += a.y * w1.w;
                acc[r][0] += a.z * w2.x; acc[r][1] += a.z * w2.y; acc[r][2] += a.z * w2.z; acc[r][3] += a.z * w2.w;
                acc[r][0] += a.w * w3.x; acc[r][1] += a.w * w3.y; acc[r][2] += a.w * w3.z; acc[r][3] += a.w * w3.w;
            }
        }

        // ELU + per-thread column partial sums (over this thread's 8 rows)
        float cs[4] = {0.f, 0.f, 0.f, 0.f};
#pragma unroll
        for (int r = 0; r < 8; r++) {
#pragma unroll
            for (int c = 0; c < 4; c++) {
                float v = acc[r][c];
                v = v > 0.f ? v : (__expf(v) - 1.f);
                cs[c] += v;
            }
        }
        float4 csv; csv.x = cs[0]; csv.y = cs[1]; csv.z = cs[2]; csv.w = cs[3];
        *(float4*)(scratch + ty * 64 + tx * 4) = csv;
        __syncthreads();
        if (tid < 64) {
            float s = 0.f;
#pragma unroll
            for (int t = 0; t < 16; t++) s += scratch[t * 64 + tid];
            g_gat[b * HID + ch * 64 + tid] = s * (1.f / 128.f);
        }
        __syncthreads();
    }
}

// ---------------------------------------------------------------------------
// out[b,t] = ffn1_out[b,:] @ ffn2_w[:,t] + ffn2_b[t]
// ---------------------------------------------------------------------------
__global__ void final_kernel(const float* __restrict__ X,
                             const float* __restrict__ W,
                             const float* __restrict__ bias,
                             float* __restrict__ out)
{
    int idx = blockIdx.x * blockDim.x + threadIdx.x;
    if (idx >= Bq * TASKS) return;
    int b = idx / TASKS, t = idx - b * TASKS;
    const float* x = X + (size_t)b * HID;
    float s = bias[t];
    for (int d = 0; d < HID; d++) s += x[d] * W[d * TASKS + t];
    out[idx] = s;
}

// ---------------------------------------------------------------------------
extern "C" void kernel_launch(void* const* d_in, const int* in_sizes, int n_in,
                              void* d_out, int out_size)
{
    const float* h        = (const float*)d_in[0];
    const int*   adj      = (const int*)d_in[1];
    const float* edge     = (const float*)d_in[2];
    const float* fp       = (const float*)d_in[3];
    const float* W_heads  = (const float*)d_in[4];
    const float* a1_heads = (const float*)d_in[5];
    const float* a2_heads = (const float*)d_in[6];
    const float* ae_heads = (const float*)d_in[7];
    const float* W_out    = (const float*)d_in[8];
    const float* a1_out   = (const float*)d_in[9];
    const float* a2_out   = (const float*)d_in[10];
    const float* ae_out   = (const float*)d_in[11];
    const float* fc1_w    = (const float*)d_in[12];
    const float* fc1_b    = (const float*)d_in[13];
    const float* fc2_w    = (const float*)d_in[14];
    const float* fc2_b    = (const float*)d_in[15];
    const float* q_w      = (const float*)d_in[16];
    const float* q_b      = (const float*)d_in[17];
    // k_w (18), k_b (19) unused: softmax over size-1 axis == 1 -> fused = q+v
    const float* v_w      = (const float*)d_in[20];
    const float* v_b      = (const float*)d_in[21];
    const float* o_w      = (const float*)d_in[22];
    const float* o_b      = (const float*)d_in[23];
    const float* ffn1_w   = (const float*)d_in[24];
    const float* ffn1_b   = (const float*)d_in[25];
    const float* ffn2_w   = (const float*)d_in[26];
    const float* ffn2_b   = (const float*)d_in[27];
    float* out = (float*)d_out;

    float *Wcat, *Wh, *x, *Wx, *gat, *fpnh, *fpn, *buf1, *buf2;
    cudaGetSymbolAddress((void**)&Wcat, g_Wcat);
    cudaGetSymbolAddress((void**)&Wh, g_Wh);
    cudaGetSymbolAddress((void**)&x, g_x);
    cudaGetSymbolAddress((void**)&Wx, g_Wx);
    cudaGetSymbolAddress((void**)&gat, g_gat);
    cudaGetSymbolAddress((void**)&fpnh, g_fpnh);
    cudaGetSymbolAddress((void**)&fpn, g_fpn);
    cudaGetSymbolAddress((void**)&buf1, g_buf1);
    cudaGetSymbolAddress((void**)&buf2, g_buf2);

    // Unconditional (no static guards allowed): pure host-side attribute set,
    // idempotent and not a stream operation, so it is graph-capture-safe.
    cudaFuncSetAttribute(attn1_kernel, cudaFuncAttributeMaxDynamicSharedMemorySize, 24832 * 4);
    cudaFuncSetAttribute(attn2_kernel, cudaFuncAttributeMaxDynamicSharedMemorySize, 25856 * 4);

    const int M1 = Bq * Nn;  // 65536

    // 1. Wcat transpose
    wcat_kernel<<<(NHEADS * F_IN * NHID + 255) / 256, 256>>>(W_heads);

    // 2. Wh = h @ Wcat   [65536,133]x[133,512]
    {
        dim3 grid(HID / 128, M1 / 128);
        sgemm_kernel<<<grid, 256>>>(h, Wcat, nullptr, Wh, M1, HID, F_IN, 0);
    }

    // 3. s1/s2
    s12_kernel<<<(Bq * NHEADS * Nn * 32) / 256, 256>>>(a1_heads, a2_heads);

    // 4. attn1 (fused softmax + AV + ELU)
    attn1_kernel<<<Bq * NHEADS, 256, 24832 * 4>>>(ae_heads, adj, edge);

    // 5. Wx = x @ W_out  [65536,512]x[512,512]
    {
        dim3 grid(HID / 128, M1 / 128);
        sgemm_kernel<<<grid, 256>>>(x, W_out, nullptr, Wx, M1, HID, HID, 0);
    }

    // 6. t1/t2
    t12_kernel<<<(Bq * Nn * 32) / 256, 256>>>(a1_out, a2_out);

    // 7. attn2 (fused softmax + AV + ELU + mean)
    attn2_kernel<<<Bq, 256, 25856 * 4>>>(ae_out, adj, edge);

    // 8. FPN
    {
        dim3 grid(HID / 128, Bq / 128);
        sgemm_kernel<<<grid, 256>>>(fp, fc1_w, fc1_b, fpnh, Bq, HID, FP_DIM, 1 | 2);
        sgemm_kernel<<<grid, 256>>>(fpnh, fc2_w, fc2_b, fpn, Bq, HID, HID, 1);
    }

    // 9. fusion: buf1 = gat@q_w + q_b;  buf1 += fpn@v_w + v_b;
    //    buf2 = relu(buf1@o_w + o_b);  buf1 = relu(buf2@ffn1 + b)
    {
        dim3 grid(HID / 128, Bq / 128);
        sgemm_kernel<<<grid, 256>>>(gat, q_w, q_b, buf1, Bq, HID, HID, 1);
        sgemm_kernel<<<grid, 256>>>(fpn, v_w, v_b, buf1, Bq, HID, HID, 1 | 4);
        sgemm_kernel<<<grid, 256>>>(buf1, o_w, o_b, buf2, Bq, HID, HID, 1 | 2);
        sgemm_kernel<<<grid, 256>>>(buf2, ffn1_w, ffn1_b, buf1, Bq, HID, HID, 1 | 2);
    }

    // 10. final projection to [512,12]
    final_kernel<<<(Bq * TASKS + 255) / 256, 256>>>(buf1, ffn2_w, ffn2_b, out);
}

// round 3
// speedup vs baseline: 1.1283x; 1.1283x over previous
#include <cuda_runtime.h>
#include <cuda_bf16.h>
#include <math.h>

// ---------------------------------------------------------------------------
// FPGNN forward, fp32 SIMT with packed FFMA2 (fma.rn.f32x2) inner loops.
// Shapes: B=512, N=128, F_IN=133, NHEADS=8, NHID=64, HID=512, FP_DIM=1489.
// ---------------------------------------------------------------------------

#define Bq 512
#define Nn 128
#define F_IN 133
#define NHEADS 8
#define NHID 64
#define HID 512
#define FP_DIM 1489
#define TASKS 12

typedef unsigned long long u64;

__device__ __forceinline__ u64 pack2(float lo, float hi) {
    u64 r; asm("mov.b64 %0, {%1,%2};" : "=l"(r) : "f"(lo), "f"(hi)); return r;
}
__device__ __forceinline__ u64 dup2(float v) { return pack2(v, v); }
__device__ __forceinline__ void fma2(u64& d, u64 a, u64 b) {
    asm("fma.rn.f32x2 %0, %1, %2, %0;" : "+l"(d) : "l"(a), "l"(b));
}
__device__ __forceinline__ float2 upk2(u64 v) {
    float2 r; asm("mov.b64 {%0,%1}, %2;" : "=f"(r.x), "=f"(r.y) : "l"(v)); return r;
}

// ---- scratch (device globals; no allocation allowed) ----
__device__ float g_Wcat[F_IN * HID];
__device__ float g_Wh[(size_t)Bq * Nn * HID];
__device__ float g_s1[Bq * NHEADS * Nn];
__device__ float g_s2[Bq * NHEADS * Nn];
__device__ float g_x[(size_t)Bq * Nn * HID];
__device__ float g_Wx[(size_t)Bq * Nn * HID];
__device__ float g_t1[Bq * Nn];
__device__ float g_t2[Bq * Nn];
__device__ float g_gat[Bq * HID];
__device__ float g_fpnh[Bq * HID];
__device__ float g_fpn[Bq * HID];
__device__ float g_buf1[Bq * HID];
__device__ float g_buf2[Bq * HID];

// ---------------------------------------------------------------------------
// Tiled SGEMM with FFMA2: C[M,N] = A[M,K] @ B[K,N] (+bias)(+relu)(+accum)
// flags: 1 = add bias, 2 = relu, 4 = accumulate into existing C
// BM=BN=128, BK=8, 256 threads, 8x8 per-thread tile (as 8x4 f32x2 pairs).
// Requires M % 128 == 0 and N % 128 == 0 (true at every call site).
// ---------------------------------------------------------------------------
__global__ __launch_bounds__(256) void sgemm_kernel(
    const float* __restrict__ A, const float* __restrict__ B,
    const float* __restrict__ bias, float* __restrict__ C,
    int M, int N, int K, int flags)
{
    __shared__ float As[8][128];
    __shared__ float Bs[8][128];

    int tid = threadIdx.x;
    int bm = blockIdx.y * 128;
    int bn = blockIdx.x * 128;
    int tx = tid & 15;          // cols tx*8..+7
    int ty = tid >> 4;          // rows ty*8..+7

    int aRow = tid >> 1;        // 0..127
    int aCol = (tid & 1) * 4;   // 0 or 4
    int bRow = tid >> 5;        // 0..7
    int bCol = (tid & 31) * 4;  // 0..124

    u64 acc[8][4];
#pragma unroll
    for (int i = 0; i < 8; i++)
#pragma unroll
        for (int j = 0; j < 4; j++) acc[i][j] = 0ull;

    for (int k0 = 0; k0 < K; k0 += 8) {
        int row = bm + aRow;
#pragma unroll
        for (int i = 0; i < 4; i++) {
            int kk = k0 + aCol + i;
            float v = 0.f;
            if (kk < K) v = A[(size_t)row * K + kk];
            As[aCol + i][aRow] = v;
        }
        {
            int kk = k0 + bRow;
            float4 v = make_float4(0.f, 0.f, 0.f, 0.f);
            if (kk < K) v = *(const float4*)(B + (size_t)kk * N + bn + bCol);
            *(float4*)&Bs[bRow][bCol] = v;
        }
        __syncthreads();
#pragma unroll
        for (int kk = 0; kk < 8; kk++) {
            u64 b2[4];
#pragma unroll
            for (int j = 0; j < 4; j++)
                b2[j] = *(const u64*)&Bs[kk][tx * 8 + j * 2];
            float a0[8];
#pragma unroll
            for (int i = 0; i < 8; i++) a0[i] = As[kk][ty * 8 + i];
#pragma unroll
            for (int i = 0; i < 8; i++) {
                u64 ad = dup2(a0[i]);
#pragma unroll
                for (int j = 0; j < 4; j++) fma2(acc[i][j], ad, b2[j]);
            }
        }
        __syncthreads();
    }

#pragma unroll
    for (int i = 0; i < 8; i++) {
        int row = bm + ty * 8 + i;
#pragma unroll
        for (int j = 0; j < 4; j++) {
            int col = bn + tx * 8 + j * 2;
            float2 v = upk2(acc[i][j]);
            if (flags & 4) {
                float2 c = *(const float2*)&C[(size_t)row * N + col];
                v.x += c.x; v.y += c.y;
            }
            if (flags & 1) { v.x += bias[col]; v.y += bias[col + 1]; }
            if (flags & 2) { v.x = fmaxf(v.x, 0.f); v.y = fmaxf(v.y, 0.f); }
            *(float2*)&C[(size_t)row * N + col] = v;
        }
    }
}

// ---------------------------------------------------------------------------
// W_heads [8,133,64] -> Wcat [133, 512]
// ---------------------------------------------------------------------------
__global__ void wcat_kernel(const float* __restrict__ W_heads)
{
    int idx = blockIdx.x * blockDim.x + threadIdx.x;
    if (idx >= NHEADS * F_IN * NHID) return;
    int h = idx / (F_IN * NHID);
    int rem = idx - h * (F_IN * NHID);
    int f = rem / NHID;
    int d = rem - f * NHID;
    g_Wcat[f * HID + h * NHID + d] = W_heads[idx];
}

// ---------------------------------------------------------------------------
// s1/s2 head scores (warp per row, 64-length dot)
// ---------------------------------------------------------------------------
__global__ __launch_bounds__(256) void s12_kernel(
    const float* __restrict__ a1, const float* __restrict__ a2)
{
    int gw = (blockIdx.x * blockDim.x + threadIdx.x) >> 5;
    int lane = threadIdx.x & 31;
    if (gw >= Bq * NHEADS * Nn) return;
    int n  = gw & 127;
    int hh = (gw >> 7) & 7;
    int b  = gw >> 10;
    const float* row = g_Wh + ((size_t)b * Nn + n) * HID + hh * NHID;
    const float* av1 = a1 + hh * NHID;
    const float* av2 = a2 + hh * NHID;
    float x0 = row[lane], x1 = row[lane + 32];
    float r1 = x0 * av1[lane] + x1 * av1[lane + 32];
    float r2 = x0 * av2[lane] + x1 * av2[lane + 32];
#pragma unroll
    for (int o = 16; o; o >>= 1) {
        r1 += __shfl_xor_sync(0xffffffffu, r1, o);
        r2 += __shfl_xor_sync(0xffffffffu, r2, o);
    }
    if (lane == 0) {
        int o = (b * NHEADS + hh) * Nn + n;
        g_s1[o] = r1;
        g_s2[o] = r2;
    }
}

// ---------------------------------------------------------------------------
// t1/t2 output-layer scores (warp per row, 512-length dot)
// ---------------------------------------------------------------------------
__global__ __launch_bounds__(256) void t12_kernel(
    const float* __restrict__ a1, const float* __restrict__ a2)
{
    int gw = (blockIdx.x * blockDim.x + threadIdx.x) >> 5;
    int lane = threadIdx.x & 31;
    if (gw >= Bq * Nn) return;
    const float* row = g_Wx + (size_t)gw * HID;
    float r1 = 0.f, r2 = 0.f;
#pragma unroll
    for (int c0 = 0; c0 < HID; c0 += 128) {
        float4 v = *(const float4*)(row + c0 + lane * 4);
        float4 w1 = *(const float4*)(a1 + c0 + lane * 4);
        float4 w2 = *(const float4*)(a2 + c0 + lane * 4);
        r1 += v.x * w1.x + v.y * w1.y + v.z * w1.z + v.w * w1.w;
        r2 += v.x * w2.x + v.y * w2.y + v.z * w2.z + v.w * w2.w;
    }
#pragma unroll
    for (int o = 16; o; o >>= 1) {
        r1 += __shfl_xor_sync(0xffffffffu, r1, o);
        r2 += __shfl_xor_sync(0xffffffffu, r2, o);
    }
    if (lane == 0) { g_t1[gw] = r1; g_t2[gw] = r2; }
}

// ---------------------------------------------------------------------------
// attn1: per-(b,h) block. Masked-leaky softmax in SMEM + att@Wh (FFMA2) + ELU
// -> x[b,n,h*64+d]
// ---------------------------------------------------------------------------
__global__ __launch_bounds__(256) void attn1_kernel(
    const float* __restrict__ ae_heads, const int* __restrict__ adj,
    const float* __restrict__ edge)
{
    extern __shared__ float sm[];
    float* sWh  = sm;            // 8192 floats
    float* sAtt = sm + 8192;     // 16384 floats
    float* ss1  = sm + 24576;    // 128
    float* ss2  = sm + 24704;    // 128

    int tid = threadIdx.x;
    int bh = blockIdx.x;
    int hh = bh & 7, b = bh >> 3;
    float ae = ae_heads[hh];

    const float* whp = g_Wh + (size_t)b * Nn * HID + hh * NHID;
    for (int i = tid; i < 128 * 16; i += 256) {
        int r = i >> 4, c = i & 15;
        ((float4*)sWh)[r * 16 + c] = *((const float4*)(whp + (size_t)r * HID) + c);
    }
    if (tid < 128) {
        ss1[tid] = g_s1[bh * Nn + tid];
        ss2[tid] = g_s2[bh * Nn + tid];
    }
    __syncthreads();

    int warp = tid >> 5, lane = tid & 31;
    for (int i = warp; i < 128; i += 8) {
        float4 ef = ((const float4*)(edge + ((size_t)b * Nn + i) * Nn))[lane];
        int4  av  = ((const int4*)(adj  + ((size_t)b * Nn + i) * Nn))[lane];
        float si = ss1[i];
        int j0 = lane * 4;
        float v0 = si + ss2[j0 + 0] + ef.x * ae; v0 = v0 >= 0.f ? v0 : 0.2f * v0; v0 = av.x > 0 ? v0 : -9e15f;
        float v1 = si + ss2[j0 + 1] + ef.y * ae; v1 = v1 >= 0.f ? v1 : 0.2f * v1; v1 = av.y > 0 ? v1 : -9e15f;
        float v2 = si + ss2[j0 + 2] + ef.z * ae; v2 = v2 >= 0.f ? v2 : 0.2f * v2; v2 = av.z > 0 ? v2 : -9e15f;
        float v3 = si + ss2[j0 + 3] + ef.w * ae; v3 = v3 >= 0.f ? v3 : 0.2f * v3; v3 = av.w > 0 ? v3 : -9e15f;
        float m = fmaxf(fmaxf(v0, v1), fmaxf(v2, v3));
#pragma unroll
        for (int o = 16; o; o >>= 1) m = fmaxf(m, __shfl_xor_sync(0xffffffffu, m, o));
        float e0 = __expf(v0 - m), e1 = __expf(v1 - m), e2 = __expf(v2 - m), e3 = __expf(v3 - m);
        float s = e0 + e1 + e2 + e3;
#pragma unroll
        for (int o = 16; o; o >>= 1) s += __shfl_xor_sync(0xffffffffu, s, o);
        float inv = 1.f / s;
        float4 out; out.x = e0 * inv; out.y = e1 * inv; out.z = e2 * inv; out.w = e3 * inv;
        ((float4*)(sAtt + i * 128))[lane] = out;
    }
    __syncthreads();

    // hp = att @ Wh : thread (tx,ty) -> rows ty*8..+7, cols tx*4..+3 (2 pairs)
    int tx = tid & 15, ty = tid >> 4;
    u64 acc[8][2];
#pragma unroll
    for (int r = 0; r < 8; r++) { acc[r][0] = 0ull; acc[r][1] = 0ull; }

    for (int j = 0; j < 128; j += 4) {
        float4 w0 = ((const float4*)(sWh + (j + 0) * 64))[tx];
        float4 w1 = ((const float4*)(sWh + (j + 1) * 64))[tx];
        float4 w2 = ((const float4*)(sWh + (j + 2) * 64))[tx];
        float4 w3 = ((const float4*)(sWh + (j + 3) * 64))[tx];
        u64 w0a = pack2(w0.x, w0.y), w0b = pack2(w0.z, w0.w);
        u64 w1a = pack2(w1.x, w1.y), w1b = pack2(w1.z, w1.w);
        u64 w2a = pack2(w2.x, w2.y), w2b = pack2(w2.z, w2.w);
        u64 w3a = pack2(w3.x, w3.y), w3b = pack2(w3.z, w3.w);
#pragma unroll
        for (int r = 0; r < 8; r++) {
            float4 a = *(const float4*)(sAtt + (ty * 8 + r) * 128 + j);
            u64 ax = dup2(a.x), ay = dup2(a.y), az = dup2(a.z), aw = dup2(a.w);
            fma2(acc[r][0], ax, w0a); fma2(acc[r][1], ax, w0b);
            fma2(acc[r][0], ay, w1a); fma2(acc[r][1], ay, w1b);
            fma2(acc[r][0], az, w2a); fma2(acc[r][1], az, w2b);
            fma2(acc[r][0], aw, w3a); fma2(acc[r][1], aw, w3b);
        }
    }

#pragma unroll
    for (int r = 0; r < 8; r++) {
        int i = ty * 8 + r;
        float2 p0 = upk2(acc[r][0]), p1 = upk2(acc[r][1]);
        float4 o;
        o.x = p0.x > 0.f ? p0.x : (__expf(p0.x) - 1.f);
        o.y = p0.y > 0.f ? p0.y : (__expf(p0.y) - 1.f);
        o.z = p1.x > 0.f ? p1.x : (__expf(p1.x) - 1.f);
        o.w = p1.y > 0.f ? p1.y : (__expf(p1.y) - 1.f);
        *(float4*)(g_x + ((size_t)b * Nn + i) * HID + hh * NHID + tx * 4) = o;
    }
}

// ---------------------------------------------------------------------------
// attn2: per-b block. Softmax in SMEM + att2@Wx (FFMA2) + ELU + node-mean.
// ---------------------------------------------------------------------------
__global__ __launch_bounds__(256) void attn2_kernel(
    const float* __restrict__ ae_out, const int* __restrict__ adj,
    const float* __restrict__ edge)
{
    extern __shared__ float sm[];
    float* sAtt    = sm;           // 16384 floats
    float* sWx     = sm + 16384;   // 8192
    float* st1     = sm + 24576;   // 128
    float* st2     = sm + 24704;   // 128
    float* scratch = sm + 24832;   // 1024 (16 x 64)

    int tid = threadIdx.x;
    int b = blockIdx.x;
    float ae = ae_out[0];

    if (tid < 128) {
        st1[tid] = g_t1[b * Nn + tid];
        st2[tid] = g_t2[b * Nn + tid];
    }
    __syncthreads();

    int warp = tid >> 5, lane = tid & 31;
    for (int i = warp; i < 128; i += 8) {
        float4 ef = ((const float4*)(edge + ((size_t)b * Nn + i) * Nn))[lane];
        int4  av  = ((const int4*)(adj  + ((size_t)b * Nn + i) * Nn))[lane];
        float si = st1[i];
        int j0 = lane * 4;
        float v0 = si + st2[j0 + 0] + ef.x * ae; v0 = v0 >= 0.f ? v0 : 0.2f * v0; v0 = av.x > 0 ? v0 : -9e15f;
        float v1 = si + st2[j0 + 1] + ef.y * ae; v1 = v1 >= 0.f ? v1 : 0.2f * v1; v1 = av.y > 0 ? v1 : -9e15f;
        float v2 = si + st2[j0 + 2] + ef.z * ae; v2 = v2 >= 0.f ? v2 : 0.2f * v2; v2 = av.z > 0 ? v2 : -9e15f;
        float v3 = si + st2[j0 + 3] + ef.w * ae; v3 = v3 >= 0.f ? v3 : 0.2f * v3; v3 = av.w > 0 ? v3 : -9e15f;
        float m = fmaxf(fmaxf(v0, v1), fmaxf(v2, v3));
#pragma unroll
        for (int o = 16; o; o >>= 1) m = fmaxf(m, __shfl_xor_sync(0xffffffffu, m, o));
        float e0 = __expf(v0 - m), e1 = __expf(v1 - m), e2 = __expf(v2 - m), e3 = __expf(v3 - m);
        float s = e0 + e1 + e2 + e3;
#pragma unroll
        for (int o = 16; o; o >>= 1) s += __shfl_xor_sync(0xffffffffu, s, o);
        float inv = 1.f / s;
        float4 out; out.x = e0 * inv; out.y = e1 * inv; out.z = e2 * inv; out.w = e3 * inv;
        ((float4*)(sAtt + i * 128))[lane] = out;
    }
    __syncthreads();

    int tx = tid & 15, ty = tid >> 4;

    for (int ch = 0; ch < 8; ch++) {
        const float* wp = g_Wx + (size_t)b * Nn * HID + ch * 64;
        for (int i = tid; i < 128 * 16; i += 256) {
            int r = i >> 4, c = i & 15;
            ((float4*)sWx)[r * 16 + c] = *((const float4*)(wp + (size_t)r * HID) + c);
        }
        __syncthreads();

        u64 acc[8][2];
#pragma unroll
        for (int r = 0; r < 8; r++) { acc[r][0] = 0ull; acc[r][1] = 0ull; }

        for (int j = 0; j < 128; j += 4) {
            float4 w0 = ((const float4*)(sWx + (j + 0) * 64))[tx];
            float4 w1 = ((const float4*)(sWx + (j + 1) * 64))[tx];
            float4 w2 = ((const float4*)(sWx + (j + 2) * 64))[tx];
            float4 w3 = ((const float4*)(sWx + (j + 3) * 64))[tx];
            u64 w0a = pack2(w0.x, w0.y), w0b = pack2(w0.z, w0.w);
            u64 w1a = pack2(w1.x, w1.y), w1b = pack2(w1.z, w1.w);
            u64 w2a = pack2(w2.x, w2.y), w2b = pack2(w2.z, w2.w);
            u64 w3a = pack2(w3.x, w3.y), w3b = pack2(w3.z, w3.w);
#pragma unroll
            for (int r = 0; r < 8; r++) {
                float4 a = *(const float4*)(sAtt + (ty * 8 + r) * 128 + j);
                u64 ax = dup2(a.x), ay = dup2(a.y), az = dup2(a.z), aw = dup2(a.w);
                fma2(acc[r][0], ax, w0a); fma2(acc[r][1], ax, w0b);
                fma2(acc[r][0], ay, w1a); fma2(acc[r][1], ay, w1b);
                fma2(acc[r][0], az, w2a); fma2(acc[r][1], az, w2b);
                fma2(acc[r][0], aw, w3a); fma2(acc[r][1], aw, w3b);
            }
        }

        // ELU + per-thread column partial sums (over this thread's 8 rows)
        float cs[4] = {0.f, 0.f, 0.f, 0.f};
#pragma unroll
        for (int r = 0; r < 8; r++) {
            float2 p0 = upk2(acc[r][0]), p1 = upk2(acc[r][1]);
            float v;
            v = p0.x; cs[0] += v > 0.f ? v : (__expf(v) - 1.f);
            v = p0.y; cs[1] += v > 0.f ? v : (__expf(v) - 1.f);
            v = p1.x; cs[2] += v > 0.f ? v : (__expf(v) - 1.f);
            v = p1.y; cs[3] += v > 0.f ? v : (__expf(v) - 1.f);
        }
        float4 csv; csv.x = cs[0]; csv.y = cs[1]; csv.z = cs[2]; csv.w = cs[3];
        *(float4*)(scratch + ty * 64 + tx * 4) = csv;
        __syncthreads();
        if (tid < 64) {
            float s = 0.f;
#pragma unroll
            for (int t = 0; t < 16; t++) s += scratch[t * 64 + tid];
            g_gat[b * HID + ch * 64 + tid] = s * (1.f / 128.f);
        }
        __syncthreads();
    }
}

// ---------------------------------------------------------------------------
// out[b,t] = ffn1_out[b,:] @ ffn2_w[:,t] + ffn2_b[t]
// ---------------------------------------------------------------------------
__global__ void final_kernel(const float* __restrict__ X,
                             const float* __restrict__ W,
                             const float* __restrict__ bias,
                             float* __restrict__ out)
{
    int idx = blockIdx.x * blockDim.x + threadIdx.x;
    if (idx >= Bq * TASKS) return;
    int b = idx / TASKS, t = idx - b * TASKS;
    const float* x = X + (size_t)b * HID;
    float s = bias[t];
    for (int d = 0; d < HID; d++) s += x[d] * W[d * TASKS + t];
    out[idx] = s;
}

// ---------------------------------------------------------------------------
extern "C" void kernel_launch(void* const* d_in, const int* in_sizes, int n_in,
                              void* d_out, int out_size)
{
    const float* h        = (const float*)d_in[0];
    const int*   adj      = (const int*)d_in[1];
    const float* edge     = (const float*)d_in[2];
    const float* fp       = (const float*)d_in[3];
    const float* W_heads  = (const float*)d_in[4];
    const float* a1_heads = (const float*)d_in[5];
    const float* a2_heads = (const float*)d_in[6];
    const float* ae_heads = (const float*)d_in[7];
    const float* W_out    = (const float*)d_in[8];
    const float* a1_out   = (const float*)d_in[9];
    const float* a2_out   = (const float*)d_in[10];
    const float* ae_out   = (const float*)d_in[11];
    const float* fc1_w    = (const float*)d_in[12];
    const float* fc1_b    = (const float*)d_in[13];
    const float* fc2_w    = (const float*)d_in[14];
    const float* fc2_b    = (const float*)d_in[15];
    const float* q_w      = (const float*)d_in[16];
    const float* q_b      = (const float*)d_in[17];
    // k_w (18), k_b (19) unused: softmax over size-1 axis == 1 -> fused = q+v
    const float* v_w      = (const float*)d_in[20];
    const float* v_b      = (const float*)d_in[21];
    const float* o_w      = (const float*)d_in[22];
    const float* o_b      = (const float*)d_in[23];
    const float* ffn1_w   = (const float*)d_in[24];
    const float* ffn1_b   = (const float*)d_in[25];
    const float* ffn2_w   = (const float*)d_in[26];
    const float* ffn2_b   = (const float*)d_in[27];
    float* out = (float*)d_out;

    float *Wcat, *Wh, *x, *Wx, *gat, *fpnh, *fpn, *buf1, *buf2;
    cudaGetSymbolAddress((void**)&Wcat, g_Wcat);
    cudaGetSymbolAddress((void**)&Wh, g_Wh);
    cudaGetSymbolAddress((void**)&x, g_x);
    cudaGetSymbolAddress((void**)&Wx, g_Wx);
    cudaGetSymbolAddress((void**)&gat, g_gat);
    cudaGetSymbolAddress((void**)&fpnh, g_fpnh);
    cudaGetSymbolAddress((void**)&fpn, g_fpn);
    cudaGetSymbolAddress((void**)&buf1, g_buf1);
    cudaGetSymbolAddress((void**)&buf2, g_buf2);

    // Unconditional (no static guards): host-side attribute set, capture-safe.
    cudaFuncSetAttribute(attn1_kernel, cudaFuncAttributeMaxDynamicSharedMemorySize, 24832 * 4);
    cudaFuncSetAttribute(attn2_kernel, cudaFuncAttributeMaxDynamicSharedMemorySize, 25856 * 4);

    const int M1 = Bq * Nn;  // 65536

    // 1. Wcat transpose
    wcat_kernel<<<(NHEADS * F_IN * NHID + 255) / 256, 256>>>(W_heads);

    // 2. Wh = h @ Wcat   [65536,133]x[133,512]
    {
        dim3 grid(HID / 128, M1 / 128);
        sgemm_kernel<<<grid, 256>>>(h, Wcat, nullptr, Wh, M1, HID, F_IN, 0);
    }

    // 3. s1/s2
    s12_kernel<<<(Bq * NHEADS * Nn * 32) / 256, 256>>>(a1_heads, a2_heads);

    // 4. attn1 (fused softmax + AV + ELU)
    attn1_kernel<<<Bq * NHEADS, 256, 24832 * 4>>>(ae_heads, adj, edge);

    // 5. Wx = x @ W_out  [65536,512]x[512,512]
    {
        dim3 grid(HID / 128, M1 / 128);
        sgemm_kernel<<<grid, 256>>>(x, W_out, nullptr, Wx, M1, HID, HID, 0);
    }

    // 6. t1/t2
    t12_kernel<<<(Bq * Nn * 32) / 256, 256>>>(a1_out, a2_out);

    // 7. attn2 (fused softmax + AV + ELU + mean)
    attn2_kernel<<<Bq, 256, 25856 * 4>>>(ae_out, adj, edge);

    // 8. FPN
    {
        dim3 grid(HID / 128, Bq / 128);
        sgemm_kernel<<<grid, 256>>>(fp, fc1_w, fc1_b, fpnh, Bq, HID, FP_DIM, 1 | 2);
        sgemm_kernel<<<grid, 256>>>(fpnh, fc2_w, fc2_b, fpn, Bq, HID, HID, 1);
    }

    // 9. fusion: buf1 = gat@q_w + q_b;  buf1 += fpn@v_w + v_b;
    //    buf2 = relu(buf1@o_w + o_b);  buf1 = relu(buf2@ffn1 + b)
    {
        dim3 grid(HID / 128, Bq / 128);
        sgemm_kernel<<<grid, 256>>>(gat, q_w, q_b, buf1, Bq, HID, HID, 1);
        sgemm_kernel<<<grid, 256>>>(fpn, v_w, v_b, buf1, Bq, HID, HID, 1 | 4);
        sgemm_kernel<<<grid, 256>>>(buf1, o_w, o_b, buf2, Bq, HID, HID, 1 | 2);
        sgemm_kernel<<<grid, 256>>>(buf2, ffn1_w, ffn1_b, buf1, Bq, HID, HID, 1 | 2);
    }

    // 10. final projection to [512,12]
    final_kernel<<<(Bq * TASKS + 255) / 256, 256>>>(buf1, ffn2_w, ffn2_b, out);
}

// round 4
// speedup vs baseline: 1.1413x; 1.0115x over previous
#include <cuda_runtime.h>
#include <cuda_bf16.h>
#include <math.h>

// ---------------------------------------------------------------------------
// FPGNN forward, fp32 SIMT, FFMA2 (fma.rn.f32x2) inner loops.
// R4: double-buffered SGEMM (1 sync / k-tile), attn1/attn2 split into 64-row
// half-blocks for 3-CTA/SM occupancy.
// ---------------------------------------------------------------------------

#define Bq 512
#define Nn 128
#define F_IN 133
#define NHEADS 8
#define NHID 64
#define HID 512
#define FP_DIM 1489
#define TASKS 12

typedef unsigned long long u64;

__device__ __forceinline__ u64 pack2(float lo, float hi) {
    u64 r; asm("mov.b64 %0, {%1,%2};" : "=l"(r) : "f"(lo), "f"(hi)); return r;
}
__device__ __forceinline__ u64 dup2(float v) { return pack2(v, v); }
__device__ __forceinline__ void fma2(u64& d, u64 a, u64 b) {
    asm("fma.rn.f32x2 %0, %1, %2, %0;" : "+l"(d) : "l"(a), "l"(b));
}
__device__ __forceinline__ float2 upk2(u64 v) {
    float2 r; asm("mov.b64 {%0,%1}, %2;" : "=f"(r.x), "=f"(r.y) : "l"(v)); return r;
}

// ---- scratch (device globals; no allocation allowed) ----
__device__ float g_Wcat[F_IN * HID];
__device__ float g_Wh[(size_t)Bq * Nn * HID];
__device__ float g_s1[Bq * NHEADS * Nn];
__device__ float g_s2[Bq * NHEADS * Nn];
__device__ float g_x[(size_t)Bq * Nn * HID];
__device__ float g_Wx[(size_t)Bq * Nn * HID];
__device__ float g_t1[Bq * Nn];
__device__ float g_t2[Bq * Nn];
__device__ float g_gatp[Bq * 2 * HID];   // per-half partial column sums
__device__ float g_gat[Bq * HID];
__device__ float g_fpnh[Bq * HID];
__device__ float g_fpn[Bq * HID];
__device__ float g_buf1[Bq * HID];
__device__ float g_buf2[Bq * HID];

// ---------------------------------------------------------------------------
// Double-buffered FFMA2 SGEMM: C[M,N] = A[M,K] @ B[K,N] (+bias)(+relu)(+acc)
// flags: 1 = add bias, 2 = relu, 4 = accumulate into existing C
// BM=BN=128, BK=8, 256 threads, 8x8 per-thread tile (8x4 f32x2 pairs).
// Requires M % 128 == 0 and N % 128 == 0.
// ---------------------------------------------------------------------------
__global__ __launch_bounds__(256) void sgemm_kernel(
    const float* __restrict__ A, const float* __restrict__ B,
    const float* __restrict__ bias, float* __restrict__ C,
    int M, int N, int K, int flags)
{
    __shared__ float As[2][8][128];
    __shared__ float Bs[2][8][128];

    int tid = threadIdx.x;
    int bm = blockIdx.y * 128;
    int bn = blockIdx.x * 128;
    int tx = tid & 15;          // cols tx*8..+7
    int ty = tid >> 4;          // rows ty*8..+7

    int aRow = tid >> 1;        // 0..127
    int aCol = (tid & 1) * 4;   // 0 or 4
    int bRow = tid >> 5;        // 0..7
    int bCol = (tid & 31) * 4;  // 0..124

    u64 acc[8][4];
#pragma unroll
    for (int i = 0; i < 8; i++)
#pragma unroll
        for (int j = 0; j < 4; j++) acc[i][j] = 0ull;

    const int Ktiles = (K + 7) / 8;
    const float* Arow = A + (size_t)(bm + aRow) * K;

    // preload tile 0
    {
#pragma unroll
        for (int i = 0; i < 4; i++) {
            int kk = aCol + i;
            As[0][aCol + i][aRow] = (kk < K) ? Arow[kk] : 0.f;
        }
        float4 v = make_float4(0.f, 0.f, 0.f, 0.f);
        if (bRow < K) v = *(const float4*)(B + (size_t)bRow * N + bn + bCol);
        *(float4*)&Bs[0][bRow][bCol] = v;
    }
    __syncthreads();

    int buf = 0;
    for (int t = 0; t < Ktiles; t++) {
        float ap[4];
        float4 bp = make_float4(0.f, 0.f, 0.f, 0.f);
        bool has_next = (t + 1 < Ktiles);
        if (has_next) {
            int k0n = (t + 1) * 8;
#pragma unroll
            for (int i = 0; i < 4; i++) {
                int kk = k0n + aCol + i;
                ap[i] = (kk < K) ? Arow[kk] : 0.f;
            }
            int kk = k0n + bRow;
            if (kk < K) bp = *(const float4*)(B + (size_t)kk * N + bn + bCol);
        }

#pragma unroll
        for (int kk = 0; kk < 8; kk++) {
            u64 b2[4];
#pragma unroll
            for (int j = 0; j < 4; j++)
                b2[j] = *(const u64*)&Bs[buf][kk][tx * 8 + j * 2];
            float a0[8];
#pragma unroll
            for (int i = 0; i < 8; i++) a0[i] = As[buf][kk][ty * 8 + i];
#pragma unroll
            for (int i = 0; i < 8; i++) {
                u64 ad = dup2(a0[i]);
#pragma unroll
                for (int j = 0; j < 4; j++) fma2(acc[i][j], ad, b2[j]);
            }
        }

        if (has_next) {
#pragma unroll
            for (int i = 0; i < 4; i++) As[buf ^ 1][aCol + i][aRow] = ap[i];
            *(float4*)&Bs[buf ^ 1][bRow][bCol] = bp;
        }
        __syncthreads();
        buf ^= 1;
    }

#pragma unroll
    for (int i = 0; i < 8; i++) {
        int row = bm + ty * 8 + i;
#pragma unroll
        for (int j = 0; j < 4; j++) {
            int col = bn + tx * 8 + j * 2;
            float2 v = upk2(acc[i][j]);
            if (flags & 4) {
                float2 c = *(const float2*)&C[(size_t)row * N + col];
                v.x += c.x; v.y += c.y;
            }
            if (flags & 1) { v.x += bias[col]; v.y += bias[col + 1]; }
            if (flags & 2) { v.x = fmaxf(v.x, 0.f); v.y = fmaxf(v.y, 0.f); }
            *(float2*)&C[(size_t)row * N + col] = v;
        }
    }
}

// ---------------------------------------------------------------------------
// W_heads [8,133,64] -> Wcat [133, 512]
// ---------------------------------------------------------------------------
__global__ void wcat_kernel(const float* __restrict__ W_heads)
{
    int idx = blockIdx.x * blockDim.x + threadIdx.x;
    if (idx >= NHEADS * F_IN * NHID) return;
    int h = idx / (F_IN * NHID);
    int rem = idx - h * (F_IN * NHID);
    int f = rem / NHID;
    int d = rem - f * NHID;
    g_Wcat[f * HID + h * NHID + d] = W_heads[idx];
}

// ---------------------------------------------------------------------------
// s1/s2 head scores (warp per row, 64-length dot)
// ---------------------------------------------------------------------------
__global__ __launch_bounds__(256) void s12_kernel(
    const float* __restrict__ a1, const float* __restrict__ a2)
{
    int gw = (blockIdx.x * blockDim.x + threadIdx.x) >> 5;
    int lane = threadIdx.x & 31;
    if (gw >= Bq * NHEADS * Nn) return;
    int n  = gw & 127;
    int hh = (gw >> 7) & 7;
    int b  = gw >> 10;
    const float* row = g_Wh + ((size_t)b * Nn + n) * HID + hh * NHID;
    const float* av1 = a1 + hh * NHID;
    const float* av2 = a2 + hh * NHID;
    float x0 = row[lane], x1 = row[lane + 32];
    float r1 = x0 * av1[lane] + x1 * av1[lane + 32];
    float r2 = x0 * av2[lane] + x1 * av2[lane + 32];
#pragma unroll
    for (int o = 16; o; o >>= 1) {
        r1 += __shfl_xor_sync(0xffffffffu, r1, o);
        r2 += __shfl_xor_sync(0xffffffffu, r2, o);
    }
    if (lane == 0) {
        int o = (b * NHEADS + hh) * Nn + n;
        g_s1[o] = r1;
        g_s2[o] = r2;
    }
}

// ---------------------------------------------------------------------------
// t1/t2 output-layer scores (warp per row, 512-length dot)
// ---------------------------------------------------------------------------
__global__ __launch_bounds__(256) void t12_kernel(
    const float* __restrict__ a1, const float* __restrict__ a2)
{
    int gw = (blockIdx.x * blockDim.x + threadIdx.x) >> 5;
    int lane = threadIdx.x & 31;
    if (gw >= Bq * Nn) return;
    const float* row = g_Wx + (size_t)gw * HID;
    float r1 = 0.f, r2 = 0.f;
#pragma unroll
    for (int c0 = 0; c0 < HID; c0 += 128) {
        float4 v = *(const float4*)(row + c0 + lane * 4);
        float4 w1 = *(const float4*)(a1 + c0 + lane * 4);
        float4 w2 = *(const float4*)(a2 + c0 + lane * 4);
        r1 += v.x * w1.x + v.y * w1.y + v.z * w1.z + v.w * w1.w;
        r2 += v.x * w2.x + v.y * w2.y + v.z * w2.z + v.w * w2.w;
    }
#pragma unroll
    for (int o = 16; o; o >>= 1) {
        r1 += __shfl_xor_sync(0xffffffffu, r1, o);
        r2 += __shfl_xor_sync(0xffffffffu, r2, o);
    }
    if (lane == 0) { g_t1[gw] = r1; g_t2[gw] = r2; }
}

// ---------------------------------------------------------------------------
// attn1 (split): block = (bh, half). 64 att rows per block.
// SMEM: sWh[128x64] 32KB + sAtt[64x128] 32KB + ss1[64] + ss2[128] ~= 65KB.
// ---------------------------------------------------------------------------
__global__ __launch_bounds__(256) void attn1_kernel(
    const float* __restrict__ ae_heads, const int* __restrict__ adj,
    const float* __restrict__ edge)
{
    extern __shared__ float sm[];
    float* sWh  = sm;            // 8192 floats (all 128 j-rows x 64)
    float* sAtt = sm + 8192;     // 8192 floats (64 rows x 128)
    float* ss1  = sm + 16384;    // 64
    float* ss2  = sm + 16448;    // 128

    int tid = threadIdx.x;
    int blk = blockIdx.x;
    int half = blk & 1;
    int bh = blk >> 1;
    int hh = bh & 7, b = bh >> 3;
    int i0 = half * 64;
    float ae = ae_heads[hh];

    const float* whp = g_Wh + (size_t)b * Nn * HID + hh * NHID;
    for (int i = tid; i < 128 * 16; i += 256) {
        int r = i >> 4, c = i & 15;
        ((float4*)sWh)[r * 16 + c] = *((const float4*)(whp + (size_t)r * HID) + c);
    }
    if (tid < 64)  ss1[tid] = g_s1[bh * Nn + i0 + tid];
    if (tid < 128) ss2[tid] = g_s2[bh * Nn + tid];
    __syncthreads();

    int warp = tid >> 5, lane = tid & 31;
    for (int i = warp; i < 64; i += 8) {
        int row = i0 + i;
        float4 ef = ((const float4*)(edge + ((size_t)b * Nn + row) * Nn))[lane];
        int4  av  = ((const int4*)(adj  + ((size_t)b * Nn + row) * Nn))[lane];
        float si = ss1[i];
        int j0 = lane * 4;
        float v0 = si + ss2[j0 + 0] + ef.x * ae; v0 = v0 >= 0.f ? v0 : 0.2f * v0; v0 = av.x > 0 ? v0 : -9e15f;
        float v1 = si + ss2[j0 + 1] + ef.y * ae; v1 = v1 >= 0.f ? v1 : 0.2f * v1; v1 = av.y > 0 ? v1 : -9e15f;
        float v2 = si + ss2[j0 + 2] + ef.z * ae; v2 = v2 >= 0.f ? v2 : 0.2f * v2; v2 = av.z > 0 ? v2 : -9e15f;
        float v3 = si + ss2[j0 + 3] + ef.w * ae; v3 = v3 >= 0.f ? v3 : 0.2f * v3; v3 = av.w > 0 ? v3 : -9e15f;
        float m = fmaxf(fmaxf(v0, v1), fmaxf(v2, v3));
#pragma unroll
        for (int o = 16; o; o >>= 1) m = fmaxf(m, __shfl_xor_sync(0xffffffffu, m, o));
        float e0 = __expf(v0 - m), e1 = __expf(v1 - m), e2 = __expf(v2 - m), e3 = __expf(v3 - m);
        float s = e0 + e1 + e2 + e3;
#pragma unroll
        for (int o = 16; o; o >>= 1) s += __shfl_xor_sync(0xffffffffu, s, o);
        float inv = 1.f / s;
        float4 out; out.x = e0 * inv; out.y = e1 * inv; out.z = e2 * inv; out.w = e3 * inv;
        ((float4*)(sAtt + i * 128))[lane] = out;
    }
    __syncthreads();

    // hp = att @ Wh : thread (tx,ty) -> rows ty*4..+3 (of 64), cols tx*4..+3
    int tx = tid & 15, ty = tid >> 4;
    u64 acc[4][2];
#pragma unroll
    for (int r = 0; r < 4; r++) { acc[r][0] = 0ull; acc[r][1] = 0ull; }

    for (int j = 0; j < 128; j += 4) {
        float4 w0 = ((const float4*)(sWh + (j + 0) * 64))[tx];
        float4 w1 = ((const float4*)(sWh + (j + 1) * 64))[tx];
        float4 w2 = ((const float4*)(sWh + (j + 2) * 64))[tx];
        float4 w3 = ((const float4*)(sWh + (j + 3) * 64))[tx];
        u64 w0a = pack2(w0.x, w0.y), w0b = pack2(w0.z, w0.w);
        u64 w1a = pack2(w1.x, w1.y), w1b = pack2(w1.z, w1.w);
        u64 w2a = pack2(w2.x, w2.y), w2b = pack2(w2.z, w2.w);
        u64 w3a = pack2(w3.x, w3.y), w3b = pack2(w3.z, w3.w);
#pragma unroll
        for (int r = 0; r < 4; r++) {
            float4 a = *(const float4*)(sAtt + (ty * 4 + r) * 128 + j);
            u64 ax = dup2(a.x), ay = dup2(a.y), az = dup2(a.z), aw = dup2(a.w);
            fma2(acc[r][0], ax, w0a); fma2(acc[r][1], ax, w0b);
            fma2(acc[r][0], ay, w1a); fma2(acc[r][1], ay, w1b);
            fma2(acc[r][0], az, w2a); fma2(acc[r][1], az, w2b);
            fma2(acc[r][0], aw, w3a); fma2(acc[r][1], aw, w3b);
        }
    }

#pragma unroll
    for (int r = 0; r < 4; r++) {
        int i = i0 + ty * 4 + r;
        float2 p0 = upk2(acc[r][0]), p1 = upk2(acc[r][1]);
        float4 o;
        o.x = p0.x > 0.f ? p0.x : (__expf(p0.x) - 1.f);
        o.y = p0.y > 0.f ? p0.y : (__expf(p0.y) - 1.f);
        o.z = p1.x > 0.f ? p1.x : (__expf(p1.x) - 1.f);
        o.w = p1.y > 0.f ? p1.y : (__expf(p1.y) - 1.f);
        *(float4*)(g_x + ((size_t)b * Nn + i) * HID + hh * NHID + tx * 4) = o;
    }
}

// ---------------------------------------------------------------------------
// attn2 (split): block = (b, half). 64 att rows; partial col-sums -> g_gatp.
// SMEM: sAtt[64x128] 32KB + sWx[128x64] 32KB + st1[64]+st2[128]+scratch 4KB.
// ---------------------------------------------------------------------------
__global__ __launch_bounds__(256) void attn2_kernel(
    const float* __restrict__ ae_out, const int* __restrict__ adj,
    const float* __restrict__ edge)
{
    extern __shared__ float sm[];
    float* sAtt    = sm;           // 8192 floats
    float* sWx     = sm + 8192;    // 8192 floats
    float* st1     = sm + 16384;   // 64
    float* st2     = sm + 16448;   // 128
    float* scratch = sm + 16576;   // 1024 (16 x 64)

    int tid = threadIdx.x;
    int blk = blockIdx.x;
    int half = blk & 1;
    int b = blk >> 1;
    int i0 = half * 64;
    float ae = ae_out[0];

    if (tid < 64)  st1[tid] = g_t1[b * Nn + i0 + tid];
    if (tid < 128) st2[tid] = g_t2[b * Nn + tid];
    __syncthreads();

    int warp = tid >> 5, lane = tid & 31;
    for (int i = warp; i < 64; i += 8) {
        int row = i0 + i;
        float4 ef = ((const float4*)(edge + ((size_t)b * Nn + row) * Nn))[lane];
        int4  av  = ((const int4*)(adj  + ((size_t)b * Nn + row) * Nn))[lane];
        float si = st1[i];
        int j0 = lane * 4;
        float v0 = si + st2[j0 + 0] + ef.x * ae; v0 = v0 >= 0.f ? v0 : 0.2f * v0; v0 = av.x > 0 ? v0 : -9e15f;
        float v1 = si + st2[j0 + 1] + ef.y * ae; v1 = v1 >= 0.f ? v1 : 0.2f * v1; v1 = av.y > 0 ? v1 : -9e15f;
        float v2 = si + st2[j0 + 2] + ef.z * ae; v2 = v2 >= 0.f ? v2 : 0.2f * v2; v2 = av.z > 0 ? v2 : -9e15f;
        float v3 = si + st2[j0 + 3] + ef.w * ae; v3 = v3 >= 0.f ? v3 : 0.2f * v3; v3 = av.w > 0 ? v3 : -9e15f;
        float m = fmaxf(fmaxf(v0, v1), fmaxf(v2, v3));
#pragma unroll
        for (int o = 16; o; o >>= 1) m = fmaxf(m, __shfl_xor_sync(0xffffffffu, m, o));
        float e0 = __expf(v0 - m), e1 = __expf(v1 - m), e2 = __expf(v2 - m), e3 = __expf(v3 - m);
        float s = e0 + e1 + e2 + e3;
#pragma unroll
        for (int o = 16; o; o >>= 1) s += __shfl_xor_sync(0xffffffffu, s, o);
        float inv = 1.f / s;
        float4 out; out.x = e0 * inv; out.y = e1 * inv; out.z = e2 * inv; out.w = e3 * inv;
        ((float4*)(sAtt + i * 128))[lane] = out;
    }
    __syncthreads();

    int tx = tid & 15, ty = tid >> 4;

    for (int ch = 0; ch < 8; ch++) {
        const float* wp = g_Wx + (size_t)b * Nn * HID + ch * 64;
        for (int i = tid; i < 128 * 16; i += 256) {
            int r = i >> 4, c = i & 15;
            ((float4*)sWx)[r * 16 + c] = *((const float4*)(wp + (size_t)r * HID) + c);
        }
        __syncthreads();

        u64 acc[4][2];
#pragma unroll
        for (int r = 0; r < 4; r++) { acc[r][0] = 0ull; acc[r][1] = 0ull; }

        for (int j = 0; j < 128; j += 4) {
            float4 w0 = ((const float4*)(sWx + (j + 0) * 64))[tx];
            float4 w1 = ((const float4*)(sWx + (j + 1) * 64))[tx];
            float4 w2 = ((const float4*)(sWx + (j + 2) * 64))[tx];
            float4 w3 = ((const float4*)(sWx + (j + 3) * 64))[tx];
            u64 w0a = pack2(w0.x, w0.y), w0b = pack2(w0.z, w0.w);
            u64 w1a = pack2(w1.x, w1.y), w1b = pack2(w1.z, w1.w);
            u64 w2a = pack2(w2.x, w2.y), w2b = pack2(w2.z, w2.w);
            u64 w3a = pack2(w3.x, w3.y), w3b = pack2(w3.z, w3.w);
#pragma unroll
            for (int r = 0; r < 4; r++) {
                float4 a = *(const float4*)(sAtt + (ty * 4 + r) * 128 + j);
                u64 ax = dup2(a.x), ay = dup2(a.y), az = dup2(a.z), aw = dup2(a.w);
                fma2(acc[r][0], ax, w0a); fma2(acc[r][1], ax, w0b);
                fma2(acc[r][0], ay, w1a); fma2(acc[r][1], ay, w1b);
                fma2(acc[r][0], az, w2a); fma2(acc[r][1], az, w2b);
                fma2(acc[r][0], aw, w3a); fma2(acc[r][1], aw, w3b);
            }
        }

        // ELU + per-thread column partial sums (this thread's 4 rows)
        float cs[4] = {0.f, 0.f, 0.f, 0.f};
#pragma unroll
        for (int r = 0; r < 4; r++) {
            float2 p0 = upk2(acc[r][0]), p1 = upk2(acc[r][1]);
            float v;
            v = p0.x; cs[0] += v > 0.f ? v : (__expf(v) - 1.f);
            v = p0.y; cs[1] += v > 0.f ? v : (__expf(v) - 1.f);
            v = p1.x; cs[2] += v > 0.f ? v : (__expf(v) - 1.f);
            v = p1.y; cs[3] += v > 0.f ? v : (__expf(v) - 1.f);
        }
        float4 csv; csv.x = cs[0]; csv.y = cs[1]; csv.z = cs[2]; csv.w = cs[3];
        *(float4*)(scratch + ty * 64 + tx * 4) = csv;
        __syncthreads();
        if (tid < 64) {
            float s = 0.f;
#pragma unroll
            for (int t = 0; t < 16; t++) s += scratch[t * 64 + tid];
            g_gatp[((size_t)b * 2 + half) * HID + ch * 64 + tid] = s;
        }
        __syncthreads();
    }
}

// ---------------------------------------------------------------------------
// gat[b,c] = (gatp[b,0,c] + gatp[b,1,c]) / 128
// ---------------------------------------------------------------------------
__global__ void gat_reduce_kernel()
{
    int idx = blockIdx.x * blockDim.x + threadIdx.x;
    if (idx >= Bq * HID) return;
    int b = idx >> 9, c = idx & 511;
    g_gat[idx] = (g_gatp[((size_t)b * 2) * HID + c] +
                  g_gatp[((size_t)b * 2 + 1) * HID + c]) * (1.f / 128.f);
}

// ---------------------------------------------------------------------------
// out[b,t] = ffn1_out[b,:] @ ffn2_w[:,t] + ffn2_b[t]
// ---------------------------------------------------------------------------
__global__ void final_kernel(const float* __restrict__ X,
                             const float* __restrict__ W,
                             const float* __restrict__ bias,
                             float* __restrict__ out)
{
    int idx = blockIdx.x * blockDim.x + threadIdx.x;
    if (idx >= Bq * TASKS) return;
    int b = idx / TASKS, t = idx - b * TASKS;
    const float* x = X + (size_t)b * HID;
    float s = bias[t];
    for (int d = 0; d < HID; d++) s += x[d] * W[d * TASKS + t];
    out[idx] = s;
}

// ---------------------------------------------------------------------------
extern "C" void kernel_launch(void* const* d_in, const int* in_sizes, int n_in,
                              void* d_out, int out_size)
{
    const float* h        = (const float*)d_in[0];
    const int*   adj      = (const int*)d_in[1];
    const float* edge     = (const float*)d_in[2];
    const float* fp       = (const float*)d_in[3];
    const float* W_heads  = (const float*)d_in[4];
    const float* a1_heads = (const float*)d_in[5];
    const float* a2_heads = (const float*)d_in[6];
    const float* ae_heads = (const float*)d_in[7];
    const float* W_out    = (const float*)d_in[8];
    const float* a1_out   = (const float*)d_in[9];
    const float* a2_out   = (const float*)d_in[10];
    const float* ae_out   = (const float*)d_in[11];
    const float* fc1_w    = (const float*)d_in[12];
    const float* fc1_b    = (const float*)d_in[13];
    const float* fc2_w    = (const float*)d_in[14];
    const float* fc2_b    = (const float*)d_in[15];
    const float* q_w      = (const float*)d_in[16];
    const float* q_b      = (const float*)d_in[17];
    // k_w (18), k_b (19) unused: softmax over size-1 axis == 1 -> fused = q+v
    const float* v_w      = (const float*)d_in[20];
    const float* v_b      = (const float*)d_in[21];
    const float* o_w      = (const float*)d_in[22];
    const float* o_b      = (const float*)d_in[23];
    const float* ffn1_w   = (const float*)d_in[24];
    const float* ffn1_b   = (const float*)d_in[25];
    const float* ffn2_w   = (const float*)d_in[26];
    const float* ffn2_b   = (const float*)d_in[27];
    float* out = (float*)d_out;

    float *Wh, *x, *gat, *fpnh, *fpn, *buf1, *buf2, *Wx;
    cudaGetSymbolAddress((void**)&Wh, g_Wh);
    cudaGetSymbolAddress((void**)&x, g_x);
    cudaGetSymbolAddress((void**)&Wx, g_Wx);
    cudaGetSymbolAddress((void**)&gat, g_gat);
    cudaGetSymbolAddress((void**)&fpnh, g_fpnh);
    cudaGetSymbolAddress((void**)&fpn, g_fpn);
    cudaGetSymbolAddress((void**)&buf1, g_buf1);
    cudaGetSymbolAddress((void**)&buf2, g_buf2);
    float* Wcat;
    cudaGetSymbolAddress((void**)&Wcat, g_Wcat);

    // Unconditional (no static guards): host-side attribute set, capture-safe.
    const int ATT1_SMEM = 16576 * 4;  // ~66.3 KB
    const int ATT2_SMEM = 17600 * 4;  // ~70.4 KB
    cudaFuncSetAttribute(attn1_kernel, cudaFuncAttributeMaxDynamicSharedMemorySize, ATT1_SMEM);
    cudaFuncSetAttribute(attn2_kernel, cudaFuncAttributeMaxDynamicSharedMemorySize, ATT2_SMEM);

    const int M1 = Bq * Nn;  // 65536

    // 1. Wcat transpose
    wcat_kernel<<<(NHEADS * F_IN * NHID + 255) / 256, 256>>>(W_heads);

    // 2. Wh = h @ Wcat   [65536,133]x[133,512]
    {
        dim3 grid(HID / 128, M1 / 128);
        sgemm_kernel<<<grid, 256>>>(h, Wcat, nullptr, Wh, M1, HID, F_IN, 0);
    }

    // 3. s1/s2
    s12_kernel<<<(Bq * NHEADS * Nn * 32) / 256, 256>>>(a1_heads, a2_heads);

    // 4. attn1 (fused softmax + AV + ELU), 2 half-blocks per (b,h)
    attn1_kernel<<<Bq * NHEADS * 2, 256, ATT1_SMEM>>>(ae_heads, adj, edge);

    // 5. Wx = x @ W_out  [65536,512]x[512,512]
    {
        dim3 grid(HID / 128, M1 / 128);
        sgemm_kernel<<<grid, 256>>>(x, W_out, nullptr, Wx, M1, HID, HID, 0);
    }

    // 6. t1/t2
    t12_kernel<<<(Bq * Nn * 32) / 256, 256>>>(a1_out, a2_out);

    // 7. attn2 (fused softmax + AV + ELU + partial mean), 2 halves per b
    attn2_kernel<<<Bq * 2, 256, ATT2_SMEM>>>(ae_out, adj, edge);
    gat_reduce_kernel<<<(Bq * HID + 255) / 256, 256>>>();

    // 8. FPN
    {
        dim3 grid(HID / 128, Bq / 128);
        sgemm_kernel<<<grid, 256>>>(fp, fc1_w, fc1_b, fpnh, Bq, HID, FP_DIM, 1 | 2);
        sgemm_kernel<<<grid, 256>>>(fpnh, fc2_w, fc2_b, fpn, Bq, HID, HID, 1);
    }

    // 9. fusion: buf1 = gat@q_w + q_b;  buf1 += fpn@v_w + v_b;
    //    buf2 = relu(buf1@o_w + o_b);  buf1 = relu(buf2@ffn1 + b)
    {
        dim3 grid(HID / 128, Bq / 128);
        sgemm_kernel<<<grid, 256>>>(gat, q_w, q_b, buf1, Bq, HID, HID, 1);
        sgemm_kernel<<<grid, 256>>>(fpn, v_w, v_b, buf1, Bq, HID, HID, 1 | 4);
        sgemm_kernel<<<grid, 256>>>(buf1, o_w, o_b, buf2, Bq, HID, HID, 1 | 2);
        sgemm_kernel<<<grid, 256>>>(buf2, ffn1_w, ffn1_b, buf1, Bq, HID, HID, 1 | 2);
    }

    // 10. final projection to [512,12]
    final_kernel<<<(Bq * TASKS + 255) / 256, 256>>>(buf1, ffn2_w, ffn2_b, out);
}

// round 8
// speedup vs baseline: 2.0382x; 1.7858x over previous
#include <cuda_runtime.h>
#include <cuda_bf16.h>
#include <math.h>

// ---------------------------------------------------------------------------
// FPGNN forward. R5/R6: all dense GEMMs on tensor cores (mma.sync tf32, fp32
// accum); attention kernels stay on the FFMA2 SIMT path.
// ---------------------------------------------------------------------------

#define Bq 512
#define Nn 128
#define F_IN 133
#define NHEADS 8
#define NHID 64
#define HID 512
#define FP_DIM 1489
#define TASKS 12

typedef unsigned long long u64;
typedef unsigned int u32;

__device__ __forceinline__ u64 pack2(float lo, float hi) {
    u64 r; asm("mov.b64 %0, {%1,%2};" : "=l"(r) : "f"(lo), "f"(hi)); return r;
}
__device__ __forceinline__ u64 dup2(float v) { return pack2(v, v); }
__device__ __forceinline__ void fma2(u64& d, u64 a, u64 b) {
    asm("fma.rn.f32x2 %0, %1, %2, %0;" : "+l"(d) : "l"(a), "l"(b));
}
__device__ __forceinline__ float2 upk2(u64 v) {
    float2 r; asm("mov.b64 {%0,%1}, %2;" : "=f"(r.x), "=f"(r.y) : "l"(v)); return r;
}
__device__ __forceinline__ u32 to_tf32(float f) {
    u32 r; asm("cvt.rna.tf32.f32 %0, %1;" : "=r"(r) : "f"(f)); return r;
}
__device__ __forceinline__ void mma_tf32(float* d, const u32* a, const u32* b) {
    asm volatile(
        "mma.sync.aligned.m16n8k8.row.col.f32.tf32.tf32.f32 "
        "{%0,%1,%2,%3}, {%4,%5,%6,%7}, {%8,%9}, {%0,%1,%2,%3};\n"
        : "+f"(d[0]), "+f"(d[1]), "+f"(d[2]), "+f"(d[3])
        : "r"(a[0]), "r"(a[1]), "r"(a[2]), "r"(a[3]), "r"(b[0]), "r"(b[1]));
}

// ---- scratch (device globals; no allocation allowed) ----
__device__ float g_Wcat[F_IN * HID];
__device__ float g_Wh[(size_t)Bq * Nn * HID];
__device__ float g_s1[Bq * NHEADS * Nn];
__device__ float g_s2[Bq * NHEADS * Nn];
__device__ float g_x[(size_t)Bq * Nn * HID];
__device__ float g_Wx[(size_t)Bq * Nn * HID];
__device__ float g_t1[Bq * Nn];
__device__ float g_t2[Bq * Nn];
__device__ float g_gatp[Bq * 2 * HID];
__device__ float g_gat[Bq * HID];
__device__ float g_fpnh[Bq * HID];
__device__ float g_fpn[Bq * HID];
__device__ float g_buf1[Bq * HID];
__device__ float g_buf2[Bq * HID];

// ---------------------------------------------------------------------------
// Tensor-core tf32 GEMM: C[M,N] = A[M,K] @ B[K,N] (+bias)(+relu)(+accum)
// flags: 1 = add bias, 2 = relu, 4 = accumulate into existing C
// BM=BN=128, BK=16, 256 threads = 8 warps (2x4), warp tile 64x32,
// mma m16n8k8 (4x4 subtiles per warp). Double-buffered smem.
// Requires M % 128 == 0, N % 128 == 0. K arbitrary (zero-padded).
// smem pads: A row stride 20, B row stride 136 -> conflict-free frag loads.
// ---------------------------------------------------------------------------
#define SA_STRIDE 20
#define SB_STRIDE 136

__global__ __launch_bounds__(256) void sgemm_tc_kernel(
    const float* __restrict__ A, const float* __restrict__ B,
    const float* __restrict__ bias, float* __restrict__ C,
    int M, int N, int K, int flags)
{
    __shared__ u32 sA[2][128 * SA_STRIDE];   // [m][k] tf32
    __shared__ u32 sB[2][16 * SB_STRIDE];    // [k][n] tf32

    int tid = threadIdx.x;
    int warp = tid >> 5, lane = tid & 31;
    int wr = warp >> 2, wc = warp & 3;      // warp grid 2 x 4
    int bm = blockIdx.y * 128;
    int bn = blockIdx.x * 128;

    int lr4 = lane >> 2;                    // lane/4: 0..7
    int lc4 = lane & 3;                     // lane%4: 0..3

    float acc[4][4][4];
#pragma unroll
    for (int mt = 0; mt < 4; mt++)
#pragma unroll
        for (int nt = 0; nt < 4; nt++)
#pragma unroll
            for (int i = 0; i < 4; i++) acc[mt][nt][i] = 0.f;

    const int Ktiles = (K + 15) / 16;

    int aRow0 = tid >> 2,         aK0 = (tid & 3) * 4;
    int aRow1 = (tid + 256) >> 2, aK1 = ((tid + 256) & 3) * 4;
    int bK0 = tid >> 5,           bN0 = (tid & 31) * 4;
    int bK1 = (tid + 256) >> 5,   bN1 = ((tid + 256) & 31) * 4;

    float ar[2][4], br[2][4];

    // ---- prefetch tile 0 into regs ----
    {
#pragma unroll
        for (int i = 0; i < 4; i++) {
            int k = aK0 + i;
            ar[0][i] = (k < K) ? A[(size_t)(bm + aRow0) * K + k] : 0.f;
            k = aK1 + i;
            ar[1][i] = (k < K) ? A[(size_t)(bm + aRow1) * K + k] : 0.f;
        }
        if (bK0 < K) *(float4*)br[0] = *(const float4*)(B + (size_t)bK0 * N + bn + bN0);
        else { br[0][0] = br[0][1] = br[0][2] = br[0][3] = 0.f; }
        if (bK1 < K) *(float4*)br[1] = *(const float4*)(B + (size_t)bK1 * N + bn + bN1);
        else { br[1][0] = br[1][1] = br[1][2] = br[1][3] = 0.f; }
    }
    // commit tile 0
#pragma unroll
    for (int i = 0; i < 4; i++) {
        sA[0][aRow0 * SA_STRIDE + aK0 + i] = to_tf32(ar[0][i]);
        sA[0][aRow1 * SA_STRIDE + aK1 + i] = to_tf32(ar[1][i]);
        sB[0][bK0 * SB_STRIDE + bN0 + i] = to_tf32(br[0][i]);
        sB[0][bK1 * SB_STRIDE + bN1 + i] = to_tf32(br[1][i]);
    }
    __syncthreads();

    int buf = 0;
    for (int t = 0; t < Ktiles; t++) {
        bool has_next = (t + 1 < Ktiles);
        if (has_next) {
            int k0 = (t + 1) * 16;
#pragma unroll
            for (int i = 0; i < 4; i++) {
                int k = k0 + aK0 + i;
                ar[0][i] = (k < K) ? A[(size_t)(bm + aRow0) * K + k] : 0.f;
                k = k0 + aK1 + i;
                ar[1][i] = (k < K) ? A[(size_t)(bm + aRow1) * K + k] : 0.f;
            }
            int k = k0 + bK0;
            if (k < K) *(float4*)br[0] = *(const float4*)(B + (size_t)k * N + bn + bN0);
            else { br[0][0] = br[0][1] = br[0][2] = br[0][3] = 0.f; }
            k = k0 + bK1;
            if (k < K) *(float4*)br[1] = *(const float4*)(B + (size_t)k * N + bn + bN1);
            else { br[1][0] = br[1][1] = br[1][2] = br[1][3] = 0.f; }
        }

        const u32* cA = sA[buf];
        const u32* cB = sB[buf];
#pragma unroll
        for (int kk = 0; kk < 16; kk += 8) {
            u32 afr[4][4], bfr[4][2];
#pragma unroll
            for (int mt = 0; mt < 4; mt++) {
                int r0 = wr * 64 + mt * 16 + lr4;
                int c0 = kk + lc4;
                afr[mt][0] = cA[r0 * SA_STRIDE + c0];
                afr[mt][1] = cA[(r0 + 8) * SA_STRIDE + c0];
                afr[mt][2] = cA[r0 * SA_STRIDE + c0 + 4];
                afr[mt][3] = cA[(r0 + 8) * SA_STRIDE + c0 + 4];
            }
#pragma unroll
            for (int nt = 0; nt < 4; nt++) {
                int col = wc * 32 + nt * 8 + lr4;
                bfr[nt][0] = cB[(kk + lc4) * SB_STRIDE + col];
                bfr[nt][1] = cB[(kk + lc4 + 4) * SB_STRIDE + col];
            }
#pragma unroll
            for (int mt = 0; mt < 4; mt++)
#pragma unroll
                for (int nt = 0; nt < 4; nt++)
                    mma_tf32(acc[mt][nt], afr[mt], bfr[nt]);
        }

        if (has_next) {
#pragma unroll
            for (int i = 0; i < 4; i++) {
                sA[buf ^ 1][aRow0 * SA_STRIDE + aK0 + i] = to_tf32(ar[0][i]);
                sA[buf ^ 1][aRow1 * SA_STRIDE + aK1 + i] = to_tf32(ar[1][i]);
                sB[buf ^ 1][bK0 * SB_STRIDE + bN0 + i] = to_tf32(br[0][i]);
                sB[buf ^ 1][bK1 * SB_STRIDE + bN1 + i] = to_tf32(br[1][i]);
            }
        }
        __syncthreads();
        buf ^= 1;
    }

    // ---- epilogue ----
#pragma unroll
    for (int mt = 0; mt < 4; mt++) {
#pragma unroll
        for (int nt = 0; nt < 4; nt++) {
            int col = bn + wc * 32 + nt * 8 + lc4 * 2;
#pragma unroll
            for (int half = 0; half < 2; half++) {
                int row = bm + wr * 64 + mt * 16 + lr4 + half * 8;
                float2 v = make_float2(acc[mt][nt][half * 2],
                                       acc[mt][nt][half * 2 + 1]);
                if (flags & 4) {
                    float2 c = *(const float2*)&C[(size_t)row * N + col];
                    v.x += c.x; v.y += c.y;
                }
                if (flags & 1) { v.x += bias[col]; v.y += bias[col + 1]; }
                if (flags & 2) { v.x = fmaxf(v.x, 0.f); v.y = fmaxf(v.y, 0.f); }
                *(float2*)&C[(size_t)row * N + col] = v;
            }
        }
    }
}

// ---------------------------------------------------------------------------
// W_heads [8,133,64] -> Wcat [133, 512]
// ---------------------------------------------------------------------------
__global__ void wcat_kernel(const float* __restrict__ W_heads)
{
    int idx = blockIdx.x * blockDim.x + threadIdx.x;
    if (idx >= NHEADS * F_IN * NHID) return;
    int h = idx / (F_IN * NHID);
    int rem = idx - h * (F_IN * NHID);
    int f = rem / NHID;
    int d = rem - f * NHID;
    g_Wcat[f * HID + h * NHID + d] = W_heads[idx];
}

// ---------------------------------------------------------------------------
// s1/s2 head scores (warp per row, 64-length dot)
// ---------------------------------------------------------------------------
__global__ __launch_bounds__(256) void s12_kernel(
    const float* __restrict__ a1, const float* __restrict__ a2)
{
    int gw = (blockIdx.x * blockDim.x + threadIdx.x) >> 5;
    int lane = threadIdx.x & 31;
    if (gw >= Bq * NHEADS * Nn) return;
    int n  = gw & 127;
    int hh = (gw >> 7) & 7;
    int b  = gw >> 10;
    const float* row = g_Wh + ((size_t)b * Nn + n) * HID + hh * NHID;
    const float* av1 = a1 + hh * NHID;
    const float* av2 = a2 + hh * NHID;
    float x0 = row[lane], x1 = row[lane + 32];
    float r1 = x0 * av1[lane] + x1 * av1[lane + 32];
    float r2 = x0 * av2[lane] + x1 * av2[lane + 32];
#pragma unroll
    for (int o = 16; o; o >>= 1) {
        r1 += __shfl_xor_sync(0xffffffffu, r1, o);
        r2 += __shfl_xor_sync(0xffffffffu, r2, o);
    }
    if (lane == 0) {
        int o = (b * NHEADS + hh) * Nn + n;
        g_s1[o] = r1;
        g_s2[o] = r2;
    }
}

// ---------------------------------------------------------------------------
// t1/t2 output-layer scores (warp per row, 512-length dot)
// ---------------------------------------------------------------------------
__global__ __launch_bounds__(256) void t12_kernel(
    const float* __restrict__ a1, const float* __restrict__ a2)
{
    int gw = (blockIdx.x * blockDim.x + threadIdx.x) >> 5;
    int lane = threadIdx.x & 31;
    if (gw >= Bq * Nn) return;
    const float* row = g_Wx + (size_t)gw * HID;
    float r1 = 0.f, r2 = 0.f;
#pragma unroll
    for (int c0 = 0; c0 < HID; c0 += 128) {
        float4 v = *(const float4*)(row + c0 + lane * 4);
        float4 w1 = *(const float4*)(a1 + c0 + lane * 4);
        float4 w2 = *(const float4*)(a2 + c0 + lane * 4);
        r1 += v.x * w1.x + v.y * w1.y + v.z * w1.z + v.w * w1.w;
        r2 += v.x * w2.x + v.y * w2.y + v.z * w2.z + v.w * w2.w;
    }
#pragma unroll
    for (int o = 16; o; o >>= 1) {
        r1 += __shfl_xor_sync(0xffffffffu, r1, o);
        r2 += __shfl_xor_sync(0xffffffffu, r2, o);
    }
    if (lane == 0) { g_t1[gw] = r1; g_t2[gw] = r2; }
}

// ---------------------------------------------------------------------------
// attn1 (split halves): block = (bh, half). 64 att rows per block.
// ---------------------------------------------------------------------------
__global__ __launch_bounds__(256) void attn1_kernel(
    const float* __restrict__ ae_heads, const int* __restrict__ adj,
    const float* __restrict__ edge)
{
    extern __shared__ float sm[];
    float* sWh  = sm;            // 8192 floats
    float* sAtt = sm + 8192;     // 8192 floats
    float* ss1  = sm + 16384;    // 64
    float* ss2  = sm + 16448;    // 128

    int tid = threadIdx.x;
    int blk = blockIdx.x;
    int half = blk & 1;
    int bh = blk >> 1;
    int hh = bh & 7, b = bh >> 3;
    int i0 = half * 64;
    float ae = ae_heads[hh];

    const float* whp = g_Wh + (size_t)b * Nn * HID + hh * NHID;
    for (int i = tid; i < 128 * 16; i += 256) {
        int r = i >> 4, c = i & 15;
        ((float4*)sWh)[r * 16 + c] = *((const float4*)(whp + (size_t)r * HID) + c);
    }
    if (tid < 64)  ss1[tid] = g_s1[bh * Nn + i0 + tid];
    if (tid < 128) ss2[tid] = g_s2[bh * Nn + tid];
    __syncthreads();

    int warp = tid >> 5, lane = tid & 31;
    for (int i = warp; i < 64; i += 8) {
        int row = i0 + i;
        float4 ef = ((const float4*)(edge + ((size_t)b * Nn + row) * Nn))[lane];
        int4  av  = ((const int4*)(adj  + ((size_t)b * Nn + row) * Nn))[lane];
        float si = ss1[i];
        int j0 = lane * 4;
        float v0 = si + ss2[j0 + 0] + ef.x * ae; v0 = v0 >= 0.f ? v0 : 0.2f * v0; v0 = av.x > 0 ? v0 : -9e15f;
        float v1 = si + ss2[j0 + 1] + ef.y * ae; v1 = v1 >= 0.f ? v1 : 0.2f * v1; v1 = av.y > 0 ? v1 : -9e15f;
        float v2 = si + ss2[j0 + 2] + ef.z * ae; v2 = v2 >= 0.f ? v2 : 0.2f * v2; v2 = av.z > 0 ? v2 : -9e15f;
        float v3 = si + ss2[j0 + 3] + ef.w * ae; v3 = v3 >= 0.f ? v3 : 0.2f * v3; v3 = av.w > 0 ? v3 : -9e15f;
        float m = fmaxf(fmaxf(v0, v1), fmaxf(v2, v3));
#pragma unroll
        for (int o = 16; o; o >>= 1) m = fmaxf(m, __shfl_xor_sync(0xffffffffu, m, o));
        float e0 = __expf(v0 - m), e1 = __expf(v1 - m), e2 = __expf(v2 - m), e3 = __expf(v3 - m);
        float s = e0 + e1 + e2 + e3;
#pragma unroll
        for (int o = 16; o; o >>= 1) s += __shfl_xor_sync(0xffffffffu, s, o);
        float inv = 1.f / s;
        float4 out; out.x = e0 * inv; out.y = e1 * inv; out.z = e2 * inv; out.w = e3 * inv;
        ((float4*)(sAtt + i * 128))[lane] = out;
    }
    __syncthreads();

    int tx = tid & 15, ty = tid >> 4;
    u64 acc[4][2];
#pragma unroll
    for (int r = 0; r < 4; r++) { acc[r][0] = 0ull; acc[r][1] = 0ull; }

    for (int j = 0; j < 128; j += 4) {
        float4 w0 = ((const float4*)(sWh + (j + 0) * 64))[tx];
        float4 w1 = ((const float4*)(sWh + (j + 1) * 64))[tx];
        float4 w2 = ((const float4*)(sWh + (j + 2) * 64))[tx];
        float4 w3 = ((const float4*)(sWh + (j + 3) * 64))[tx];
        u64 w0a = pack2(w0.x, w0.y), w0b = pack2(w0.z, w0.w);
        u64 w1a = pack2(w1.x, w1.y), w1b = pack2(w1.z, w1.w);
        u64 w2a = pack2(w2.x, w2.y), w2b = pack2(w2.z, w2.w);
        u64 w3a = pack2(w3.x, w3.y), w3b = pack2(w3.z, w3.w);
#pragma unroll
        for (int r = 0; r < 4; r++) {
            float4 a = *(const float4*)(sAtt + (ty * 4 + r) * 128 + j);
            u64 ax = dup2(a.x), ay = dup2(a.y), az = dup2(a.z), aw = dup2(a.w);
            fma2(acc[r][0], ax, w0a); fma2(acc[r][1], ax, w0b);
            fma2(acc[r][0], ay, w1a); fma2(acc[r][1], ay, w1b);
            fma2(acc[r][0], az, w2a); fma2(acc[r][1], az, w2b);
            fma2(acc[r][0], aw, w3a); fma2(acc[r][1], aw, w3b);
        }
    }

#pragma unroll
    for (int r = 0; r < 4; r++) {
        int i = i0 + ty * 4 + r;
        float2 p0 = upk2(acc[r][0]), p1 = upk2(acc[r][1]);
        float4 o;
        o.x = p0.x > 0.f ? p0.x : (__expf(p0.x) - 1.f);
        o.y = p0.y > 0.f ? p0.y : (__expf(p0.y) - 1.f);
        o.z = p1.x > 0.f ? p1.x : (__expf(p1.x) - 1.f);
        o.w = p1.y > 0.f ? p1.y : (__expf(p1.y) - 1.f);
        *(float4*)(g_x + ((size_t)b * Nn + i) * HID + hh * NHID + tx * 4) = o;
    }
}

// ---------------------------------------------------------------------------
// attn2 (split halves): block = (b, half). Partial col-sums -> g_gatp.
// ---------------------------------------------------------------------------
__global__ __launch_bounds__(256) void attn2_kernel(
    const float* __restrict__ ae_out, const int* __restrict__ adj,
    const float* __restrict__ edge)
{
    extern __shared__ float sm[];
    float* sAtt    = sm;           // 8192 floats
    float* sWx     = sm + 8192;    // 8192 floats
    float* st1     = sm + 16384;   // 64
    float* st2     = sm + 16448;   // 128
    float* scratch = sm + 16576;   // 1024

    int tid = threadIdx.x;
    int blk = blockIdx.x;
    int half = blk & 1;
    int b = blk >> 1;
    int i0 = half * 64;
    float ae = ae_out[0];

    if (tid < 64)  st1[tid] = g_t1[b * Nn + i0 + tid];
    if (tid < 128) st2[tid] = g_t2[b * Nn + tid];
    __syncthreads();

    int warp = tid >> 5, lane = tid & 31;
    for (int i = warp; i < 64; i += 8) {
        int row = i0 + i;
        float4 ef = ((const float4*)(edge + ((size_t)b * Nn + row) * Nn))[lane];
        int4  av  = ((const int4*)(adj  + ((size_t)b * Nn + row) * Nn))[lane];
        float si = st1[i];
        int j0 = lane * 4;
        float v0 = si + st2[j0 + 0] + ef.x * ae; v0 = v0 >= 0.f ? v0 : 0.2f * v0; v0 = av.x > 0 ? v0 : -9e15f;
        float v1 = si + st2[j0 + 1] + ef.y * ae; v1 = v1 >= 0.f ? v1 : 0.2f * v1; v1 = av.y > 0 ? v1 : -9e15f;
        float v2 = si + st2[j0 + 2] + ef.z * ae; v2 = v2 >= 0.f ? v2 : 0.2f * v2; v2 = av.z > 0 ? v2 : -9e15f;
        float v3 = si + st2[j0 + 3] + ef.w * ae; v3 = v3 >= 0.f ? v3 : 0.2f * v3; v3 = av.w > 0 ? v3 : -9e15f;
        float m = fmaxf(fmaxf(v0, v1), fmaxf(v2, v3));
#pragma unroll
        for (int o = 16; o; o >>= 1) m = fmaxf(m, __shfl_xor_sync(0xffffffffu, m, o));
        float e0 = __expf(v0 - m), e1 = __expf(v1 - m), e2 = __expf(v2 - m), e3 = __expf(v3 - m);
        float s = e0 + e1 + e2 + e3;
#pragma unroll
        for (int o = 16; o; o >>= 1) s += __shfl_xor_sync(0xffffffffu, s, o);
        float inv = 1.f / s;
        float4 out; out.x = e0 * inv; out.y = e1 * inv; out.z = e2 * inv; out.w = e3 * inv;
        ((float4*)(sAtt + i * 128))[lane] = out;
    }
    __syncthreads();

    int tx = tid & 15, ty = tid >> 4;

    for (int ch = 0; ch < 8; ch++) {
        const float* wp = g_Wx + (size_t)b * Nn * HID + ch * 64;
        for (int i = tid; i < 128 * 16; i += 256) {
            int r = i >> 4, c = i & 15;
            ((float4*)sWx)[r * 16 + c] = *((const float4*)(wp + (size_t)r * HID) + c);
        }
        __syncthreads();

        u64 acc[4][2];
#pragma unroll
        for (int r = 0; r < 4; r++) { acc[r][0] = 0ull; acc[r][1] = 0ull; }

        for (int j = 0; j < 128; j += 4) {
            float4 w0 = ((const float4*)(sWx + (j + 0) * 64))[tx];
            float4 w1 = ((const float4*)(sWx + (j + 1) * 64))[tx];
            float4 w2 = ((const float4*)(sWx + (j + 2) * 64))[tx];
            float4 w3 = ((const float4*)(sWx + (j + 3) * 64))[tx];
            u64 w0a = pack2(w0.x, w0.y), w0b = pack2(w0.z, w0.w);
            u64 w1a = pack2(w1.x, w1.y), w1b = pack2(w1.z, w1.w);
            u64 w2a = pack2(w2.x, w2.y), w2b = pack2(w2.z, w2.w);
            u64 w3a = pack2(w3.x, w3.y), w3b = pack2(w3.z, w3.w);
#pragma unroll
            for (int r = 0; r < 4; r++) {
                float4 a = *(const float4*)(sAtt + (ty * 4 + r) * 128 + j);
                u64 ax = dup2(a.x), ay = dup2(a.y), az = dup2(a.z), aw = dup2(a.w);
                fma2(acc[r][0], ax, w0a); fma2(acc[r][1], ax, w0b);
                fma2(acc[r][0], ay, w1a); fma2(acc[r][1], ay, w1b);
                fma2(acc[r][0], az, w2a); fma2(acc[r][1], az, w2b);
                fma2(acc[r][0], aw, w3a); fma2(acc[r][1], aw, w3b);
            }
        }

        float cs[4] = {0.f, 0.f, 0.f, 0.f};
#pragma unroll
        for (int r = 0; r < 4; r++) {
            float2 p0 = upk2(acc[r][0]), p1 = upk2(acc[r][1]);
            float v;
            v = p0.x; cs[0] += v > 0.f ? v : (__expf(v) - 1.f);
            v = p0.y; cs[1] += v > 0.f ? v : (__expf(v) - 1.f);
            v = p1.x; cs[2] += v > 0.f ? v : (__expf(v) - 1.f);
            v = p1.y; cs[3] += v > 0.f ? v : (__expf(v) - 1.f);
        }
        float4 csv; csv.x = cs[0]; csv.y = cs[1]; csv.z = cs[2]; csv.w = cs[3];
        *(float4*)(scratch + ty * 64 + tx * 4) = csv;
        __syncthreads();
        if (tid < 64) {
            float s = 0.f;
#pragma unroll
            for (int t = 0; t < 16; t++) s += scratch[t * 64 + tid];
            g_gatp[((size_t)b * 2 + half) * HID + ch * 64 + tid] = s;
        }
        __syncthreads();
    }
}

// ---------------------------------------------------------------------------
__global__ void gat_reduce_kernel()
{
    int idx = blockIdx.x * blockDim.x + threadIdx.x;
    if (idx >= Bq * HID) return;
    int b = idx >> 9, c = idx & 511;
    g_gat[idx] = (g_gatp[((size_t)b * 2) * HID + c] +
                  g_gatp[((size_t)b * 2 + 1) * HID + c]) * (1.f / 128.f);
}

// ---------------------------------------------------------------------------
__global__ void final_kernel(const float* __restrict__ X,
                             const float* __restrict__ W,
                             const float* __restrict__ bias,
                             float* __restrict__ out)
{
    int idx = blockIdx.x * blockDim.x + threadIdx.x;
    if (idx >= Bq * TASKS) return;
    int b = idx / TASKS, t = idx - b * TASKS;
    const float* x = X + (size_t)b * HID;
    float s = bias[t];
    for (int d = 0; d < HID; d++) s += x[d] * W[d * TASKS + t];
    out[idx] = s;
}

// ---------------------------------------------------------------------------
extern "C" void kernel_launch(void* const* d_in, const int* in_sizes, int n_in,
                              void* d_out, int out_size)
{
    const float* h        = (const float*)d_in[0];
    const int*   adj      = (const int*)d_in[1];
    const float* edge     = (const float*)d_in[2];
    const float* fp       = (const float*)d_in[3];
    const float* W_heads  = (const float*)d_in[4];
    const float* a1_heads = (const float*)d_in[5];
    const float* a2_heads = (const float*)d_in[6];
    const float* ae_heads = (const float*)d_in[7];
    const float* W_out    = (const float*)d_in[8];
    const float* a1_out   = (const float*)d_in[9];
    const float* a2_out   = (const float*)d_in[10];
    const float* ae_out   = (const float*)d_in[11];
    const float* fc1_w    = (const float*)d_in[12];
    const float* fc1_b    = (const float*)d_in[13];
    const float* fc2_w    = (const float*)d_in[14];
    const float* fc2_b    = (const float*)d_in[15];
    const float* q_w      = (const float*)d_in[16];
    const float* q_b      = (const float*)d_in[17];
    // k_w (18), k_b (19) unused: softmax over size-1 axis == 1 -> fused = q+v
    const float* v_w      = (const float*)d_in[20];
    const float* v_b      = (const float*)d_in[21];
    const float* o_w      = (const float*)d_in[22];
    const float* o_b      = (const float*)d_in[23];
    const float* ffn1_w   = (const float*)d_in[24];
    const float* ffn1_b   = (const float*)d_in[25];
    const float* ffn2_w   = (const float*)d_in[26];
    const float* ffn2_b   = (const float*)d_in[27];
    float* out = (float*)d_out;

    float *Wh, *x, *gat, *fpnh, *fpn, *buf1, *buf2, *Wx, *Wcat;
    cudaGetSymbolAddress((void**)&Wh, g_Wh);
    cudaGetSymbolAddress((void**)&x, g_x);
    cudaGetSymbolAddress((void**)&Wx, g_Wx);
    cudaGetSymbolAddress((void**)&gat, g_gat);
    cudaGetSymbolAddress((void**)&fpnh, g_fpnh);
    cudaGetSymbolAddress((void**)&fpn, g_fpn);
    cudaGetSymbolAddress((void**)&buf1, g_buf1);
    cudaGetSymbolAddress((void**)&buf2, g_buf2);
    cudaGetSymbolAddress((void**)&Wcat, g_Wcat);

    const int ATT1_SMEM = 16576 * 4;
    const int ATT2_SMEM = 17600 * 4;
    cudaFuncSetAttribute(attn1_kernel, cudaFuncAttributeMaxDynamicSharedMemorySize, ATT1_SMEM);
    cudaFuncSetAttribute(attn2_kernel, cudaFuncAttributeMaxDynamicSharedMemorySize, ATT2_SMEM);

    const int M1 = Bq * Nn;  // 65536

    // 1. Wcat transpose
    wcat_kernel<<<(NHEADS * F_IN * NHID + 255) / 256, 256>>>(W_heads);

    // 2. Wh = h @ Wcat
    {
        dim3 grid(HID / 128, M1 / 128);
        sgemm_tc_kernel<<<grid, 256>>>(h, Wcat, nullptr, Wh, M1, HID, F_IN, 0);
    }

    // 3. s1/s2
    s12_kernel<<<(Bq * NHEADS * Nn * 32) / 256, 256>>>(a1_heads, a2_heads);

    // 4. attn1
    attn1_kernel<<<Bq * NHEADS * 2, 256, ATT1_SMEM>>>(ae_heads, adj, edge);

    // 5. Wx = x @ W_out
    {
        dim3 grid(HID / 128, M1 / 128);
        sgemm_tc_kernel<<<grid, 256>>>(x, W_out, nullptr, Wx, M1, HID, HID, 0);
    }

    // 6. t1/t2
    t12_kernel<<<(Bq * Nn * 32) / 256, 256>>>(a1_out, a2_out);

    // 7. attn2 + mean reduce
    attn2_kernel<<<Bq * 2, 256, ATT2_SMEM>>>(ae_out, adj, edge);
    gat_reduce_kernel<<<(Bq * HID + 255) / 256, 256>>>();

    // 8. FPN
    {
        dim3 grid(HID / 128, Bq / 128);
        sgemm_tc_kernel<<<grid, 256>>>(fp, fc1_w, fc1_b, fpnh, Bq, HID, FP_DIM, 1 | 2);
        sgemm_tc_kernel<<<grid, 256>>>(fpnh, fc2_w, fc2_b, fpn, Bq, HID, HID, 1);
    }

    // 9. fusion + FFN
    {
        dim3 grid(HID / 128, Bq / 128);
        sgemm_tc_kernel<<<grid, 256>>>(gat, q_w, q_b, buf1, Bq, HID, HID, 1);
        sgemm_tc_kernel<<<grid, 256>>>(fpn, v_w, v_b, buf1, Bq, HID, HID, 1 | 4);
        sgemm_tc_kernel<<<grid, 256>>>(buf1, o_w, o_b, buf2, Bq, HID, HID, 1 | 2);
        sgemm_tc_kernel<<<grid, 256>>>(buf2, ffn1_w, ffn1_b, buf1, Bq, HID, HID, 1 | 2);
    }

    // 10. final projection
    final_kernel<<<(Bq * TASKS + 255) / 256, 256>>>(buf1, ffn2_w, ffn2_b, out);
}